// round 6
// baseline (speedup 1.0000x reference)
#include <cuda_runtime.h>
#include <math.h>

#define B_    32
#define T_    512
#define IN_   256
#define PRE_  512
#define LH_   512
#define NHID  1024
#define ACTH  512
#define NPOL  64
#define MTOT  (B_ * T_)      // 16384
#define G4    (4 * NHID)     // 4096

// ---------------- scratch (device globals; no allocation allowed) ----------------
__device__ float g_h [(size_t)MTOT * PRE_];
__device__ float g_u [(size_t)MTOT * LH_];
__device__ float g_xg[(size_t)MTOT * G4];
__device__ float g_hs[(size_t)MTOT * NHID];
__device__ float g_a [(size_t)MTOT * ACTH];
__device__ float g_v [(size_t)MTOT * ACTH];
__device__ float g_hstA[B_ * NHID];
__device__ float g_hstB[B_ * NHID];
__device__ float g_cst [B_ * NHID];

// ---------------- zero init for recurrent state ----------------
__global__ void zero_states(float* a, float* c, int n) {
    int i = blockIdx.x * blockDim.x + threadIdx.x;
    if (i < n) { a[i] = 0.0f; c[i] = 0.0f; }
}

// ---------------- generic tiled SGEMM: C[m,n] = act(sum_k A[m,k]*W[n,k] + b1[n] (+ b2[n])) ----
// A: [M,K] row-major, W: [N,K] row-major. BM=BN=64, BK=16, 256 threads, 4x4 micro-tile.
#define BM 64
#define BN 64
#define BK 16

template<bool RELU>
__global__ void sgemm_bias(const float* __restrict__ A, const float* __restrict__ W,
                           const float* __restrict__ bias1, const float* __restrict__ bias2,
                           float* __restrict__ C, int M, int N, int K) {
    __shared__ float As[BK][BM + 4];
    __shared__ float Ws[BK][BN + 4];

    const int tid = threadIdx.x;
    const int tx = tid & 15;          // n micro index
    const int ty = tid >> 4;          // m micro index
    const int m0 = blockIdx.y * BM;
    const int n0 = blockIdx.x * BN;

    const int lrow = tid >> 2;        // 0..63
    const int lkq  = (tid & 3) * 4;   // 0,4,8,12

    float acc[4][4] = {};

    for (int k0 = 0; k0 < K; k0 += BK) {
        float4 av = *(const float4*)&A[(size_t)(m0 + lrow) * K + k0 + lkq];
        float4 wv = *(const float4*)&W[(size_t)(n0 + lrow) * K + k0 + lkq];
        As[lkq + 0][lrow] = av.x; As[lkq + 1][lrow] = av.y;
        As[lkq + 2][lrow] = av.z; As[lkq + 3][lrow] = av.w;
        Ws[lkq + 0][lrow] = wv.x; Ws[lkq + 1][lrow] = wv.y;
        Ws[lkq + 2][lrow] = wv.z; Ws[lkq + 3][lrow] = wv.w;
        __syncthreads();

        #pragma unroll
        for (int kk = 0; kk < BK; kk++) {
            float4 a4 = *(const float4*)&As[kk][ty * 4];
            float4 w4 = *(const float4*)&Ws[kk][tx * 4];
            float am[4] = {a4.x, a4.y, a4.z, a4.w};
            float wn[4] = {w4.x, w4.y, w4.z, w4.w};
            #pragma unroll
            for (int i = 0; i < 4; i++)
                #pragma unroll
                for (int j = 0; j < 4; j++)
                    acc[i][j] = fmaf(am[i], wn[j], acc[i][j]);
        }
        __syncthreads();
    }

    float4 bv = *(const float4*)&bias1[n0 + tx * 4];
    if (bias2) {
        float4 b2 = *(const float4*)&bias2[n0 + tx * 4];
        bv.x += b2.x; bv.y += b2.y; bv.z += b2.z; bv.w += b2.w;
    }
    float bn[4] = {bv.x, bv.y, bv.z, bv.w};

    #pragma unroll
    for (int i = 0; i < 4; i++) {
        float4 o;
        float* op = &o.x;
        #pragma unroll
        for (int j = 0; j < 4; j++) {
            float val = acc[i][j] + bn[j];
            if (RELU) val = fmaxf(val, 0.0f);
            op[j] = val;
        }
        *(float4*)&C[(size_t)(m0 + ty * 4 + i) * N + n0 + tx * 4] = o;
    }
}

// ---------------- LSTM step: gates = xg[:,t,:] + h @ Whh^T, cell update ----------------
// grid = 128 blocks (8 hidden units each), 256 threads.
// warp w owns j = blockIdx.x*8 + w, all 4 gates; lane = batch index.
#define KC 128

__global__ void lstm_step(const float* __restrict__ Whh,
                          const float* __restrict__ xg,
                          const float* __restrict__ hin,
                          float* __restrict__ hout,
                          float* __restrict__ cst,
                          float* __restrict__ hs,
                          int t) {
    __shared__ float ht[KC][33];   // [kk][b], pad for conflict-free compute reads

    const int tid  = threadIdx.x;
    const int lane = tid & 31;     // batch
    const int w    = tid >> 5;     // warp -> hidden unit within block
    const int j    = blockIdx.x * 8 + w;

    const float* w0 = Whh + (size_t)(0 * NHID + j) * NHID;
    const float* w1 = Whh + (size_t)(1 * NHID + j) * NHID;
    const float* w2 = Whh + (size_t)(2 * NHID + j) * NHID;
    const float* w3 = Whh + (size_t)(3 * NHID + j) * NHID;

    float a0 = 0.f, a1 = 0.f, a2 = 0.f, a3 = 0.f;

    for (int kc = 0; kc < NHID; kc += KC) {
        // stage h chunk [32 x 128] into shared, transposed to [kk][b]
        #pragma unroll
        for (int it = 0; it < 4; it++) {
            int idx = tid + it * 256;      // 0..1023 float4 slots
            int b   = idx >> 5;            // 0..31
            int kq  = (idx & 31) * 4;      // 0..124
            float4 v = *(const float4*)&hin[b * NHID + kc + kq];
            ht[kq + 0][b] = v.x; ht[kq + 1][b] = v.y;
            ht[kq + 2][b] = v.z; ht[kq + 3][b] = v.w;
        }
        __syncthreads();

        #pragma unroll 2
        for (int kk = 0; kk < KC; kk += 4) {
            float4 v0 = *(const float4*)&w0[kc + kk];
            float4 v1 = *(const float4*)&w1[kc + kk];
            float4 v2 = *(const float4*)&w2[kc + kk];
            float4 v3 = *(const float4*)&w3[kc + kk];
            float h0 = ht[kk + 0][lane];
            float h1 = ht[kk + 1][lane];
            float h2 = ht[kk + 2][lane];
            float h3 = ht[kk + 3][lane];
            a0 = fmaf(v0.x, h0, a0); a0 = fmaf(v0.y, h1, a0);
            a0 = fmaf(v0.z, h2, a0); a0 = fmaf(v0.w, h3, a0);
            a1 = fmaf(v1.x, h0, a1); a1 = fmaf(v1.y, h1, a1);
            a1 = fmaf(v1.z, h2, a1); a1 = fmaf(v1.w, h3, a1);
            a2 = fmaf(v2.x, h0, a2); a2 = fmaf(v2.y, h1, a2);
            a2 = fmaf(v2.z, h2, a2); a2 = fmaf(v2.w, h3, a2);
            a3 = fmaf(v3.x, h0, a3); a3 = fmaf(v3.y, h1, a3);
            a3 = fmaf(v3.z, h2, a3); a3 = fmaf(v3.w, h3, a3);
        }
        __syncthreads();
    }

    // cell update: thread (lane=b, warp=j) owns all four gates
    const int b = lane;
    const float* xr = xg + ((size_t)b * T_ + t) * G4;
    float gi = a0 + xr[0 * NHID + j];
    float gf = a1 + xr[1 * NHID + j];
    float gg = a2 + xr[2 * NHID + j];
    float go = a3 + xr[3 * NHID + j];

    float si = 1.0f / (1.0f + expf(-gi));
    float sf = 1.0f / (1.0f + expf(-gf));
    float so = 1.0f / (1.0f + expf(-go));

    float c = sf * cst[b * NHID + j] + si * tanhf(gg);
    float h = so * tanhf(c);

    cst[b * NHID + j] = c;
    hout[b * NHID + j] = h;
    hs[((size_t)b * T_ + t) * NHID + j] = h;
}

// ---------------- softmax over last dim (64) in place ----------------
__global__ void softmax64(float* __restrict__ logits) {
    const int row  = blockIdx.x * 4 + (threadIdx.x >> 5);
    const int lane = threadIdx.x & 31;
    float* p = logits + (size_t)row * NPOL;
    float v0 = p[lane], v1 = p[lane + 32];
    float m = fmaxf(v0, v1);
    #pragma unroll
    for (int off = 16; off > 0; off >>= 1)
        m = fmaxf(m, __shfl_xor_sync(0xffffffffu, m, off));
    float e0 = expf(v0 - m), e1 = expf(v1 - m);
    float s = e0 + e1;
    #pragma unroll
    for (int off = 16; off > 0; off >>= 1)
        s += __shfl_xor_sync(0xffffffffu, s, off);
    float inv = 1.0f / s;
    p[lane] = e0 * inv;
    p[lane + 32] = e1 * inv;
}

// ---------------- value head: out[m] = dot(V[m,:512], w) + b[0] ----------------
__global__ void matvec_val(const float* __restrict__ V, const float* __restrict__ w,
                           const float* __restrict__ bias, float* __restrict__ out) {
    const int row  = blockIdx.x * 8 + (threadIdx.x >> 5);
    const int lane = threadIdx.x & 31;
    const float* vr = V + (size_t)row * ACTH;
    float s = 0.0f;
    #pragma unroll
    for (int q = 0; q < 4; q++) {
        int k = q * 128 + lane * 4;
        float4 a = *(const float4*)&vr[k];
        float4 b = *(const float4*)&w[k];
        s = fmaf(a.x, b.x, s); s = fmaf(a.y, b.y, s);
        s = fmaf(a.z, b.z, s); s = fmaf(a.w, b.w, s);
    }
    #pragma unroll
    for (int off = 16; off > 0; off >>= 1)
        s += __shfl_xor_sync(0xffffffffu, s, off);
    if (lane == 0) out[row] = s + bias[0];
}

// ---------------- launch ----------------
extern "C" void kernel_launch(void* const* d_in, const int* in_sizes, int n_in,
                              void* d_out, int out_size) {
    const float* x        = (const float*)d_in[0];
    const float* pre_W0   = (const float*)d_in[1];
    const float* pre_b0   = (const float*)d_in[2];
    const float* pre_W1   = (const float*)d_in[3];
    const float* pre_b1   = (const float*)d_in[4];
    const float* w_ih     = (const float*)d_in[5];
    const float* w_hh     = (const float*)d_in[6];
    const float* b_ih     = (const float*)d_in[7];
    const float* b_hh     = (const float*)d_in[8];
    const float* act_W0   = (const float*)d_in[9];
    const float* act_b0   = (const float*)d_in[10];
    const float* act_W1   = (const float*)d_in[11];
    const float* act_b1   = (const float*)d_in[12];
    const float* val_W0   = (const float*)d_in[13];
    const float* val_b0   = (const float*)d_in[14];
    const float* val_W1   = (const float*)d_in[15];
    const float* val_b1   = (const float*)d_in[16];

    float* out_probs = (float*)d_out;
    float* out_value = (float*)d_out + (size_t)MTOT * NPOL;

    float *pH, *pU, *pXG, *pHS, *pA, *pV, *pHA, *pHB, *pC;
    cudaGetSymbolAddress((void**)&pH,  g_h);
    cudaGetSymbolAddress((void**)&pU,  g_u);
    cudaGetSymbolAddress((void**)&pXG, g_xg);
    cudaGetSymbolAddress((void**)&pHS, g_hs);
    cudaGetSymbolAddress((void**)&pA,  g_a);
    cudaGetSymbolAddress((void**)&pV,  g_v);
    cudaGetSymbolAddress((void**)&pHA, g_hstA);
    cudaGetSymbolAddress((void**)&pHB, g_hstB);
    cudaGetSymbolAddress((void**)&pC,  g_cst);

    // zero recurrent state
    zero_states<<<(B_ * NHID + 255) / 256, 256>>>(pHA, pC, B_ * NHID);

    // pre_dnn
    sgemm_bias<true ><<<dim3(PRE_ / BN, MTOT / BM), 256>>>(x,  pre_W0, pre_b0, nullptr, pH, MTOT, PRE_, IN_);
    sgemm_bias<false><<<dim3(LH_  / BN, MTOT / BM), 256>>>(pH, pre_W1, pre_b1, nullptr, pU, MTOT, LH_, PRE_);

    // input contribution to gates (+ both biases)
    sgemm_bias<false><<<dim3(G4 / BN, MTOT / BM), 256>>>(pU, w_ih, b_ih, b_hh, pXG, MTOT, G4, LH_);

    // sequential recurrence, double-buffered h state
    for (int t = 0; t < T_; t++) {
        const float* hin = (t & 1) ? pHB : pHA;
        float*       hot = (t & 1) ? pHA : pHB;
        lstm_step<<<NHID / 8, 256>>>(w_hh, pXG, hin, hot, pC, pHS, t);
    }

    // policy head
    sgemm_bias<true ><<<dim3(ACTH / BN, MTOT / BM), 256>>>(pHS, act_W0, act_b0, nullptr, pA, MTOT, ACTH, NHID);
    sgemm_bias<false><<<dim3(NPOL / BN, MTOT / BM), 256>>>(pA, act_W1, act_b1, nullptr, out_probs, MTOT, NPOL, ACTH);
    softmax64<<<MTOT / 4, 128>>>(out_probs);

    // value head
    sgemm_bias<true ><<<dim3(ACTH / BN, MTOT / BM), 256>>>(pHS, val_W0, val_b0, nullptr, pV, MTOT, ACTH, NHID);
    matvec_val<<<MTOT / 8, 256>>>(pV, val_W1, val_b1, out_value);
}

// round 7
// speedup vs baseline: 2.6662x; 2.6662x over previous
#include <cuda_runtime.h>
#include <math.h>

#define B_    32
#define T_    512
#define IN_   256
#define PRE_  512
#define LH_   512
#define NHID  1024
#define ACTH  512
#define NPOL  64
#define MTOT  (B_ * T_)      // 16384
#define G4    (4 * NHID)     // 4096

#define NBLK  128            // persistent blocks (<= 148 SMs, guaranteed co-resident)
#define TPB   256
#define KC    128            // h chunk along K

// ---------------- scratch (device globals; no allocation allowed) ----------------
__device__ float g_h [(size_t)MTOT * PRE_];
__device__ float g_u [(size_t)MTOT * LH_];
__device__ float g_xg[(size_t)MTOT * G4];
__device__ float g_hs[(size_t)MTOT * NHID];
__device__ float g_a [(size_t)MTOT * ACTH];
__device__ float g_v [(size_t)MTOT * ACTH];
__device__ float g_hstA[B_ * NHID];
__device__ float g_hstB[B_ * NHID];
__device__ unsigned g_bar;

__global__ void reset_bar() { g_bar = 0u; }

// ---------------- packed f32x2 helpers ----------------
__device__ __forceinline__ unsigned long long pk2(float lo, float hi) {
    unsigned long long r;
    asm("mov.b64 %0, {%1, %2};" : "=l"(r) : "f"(lo), "f"(hi));
    return r;
}
__device__ __forceinline__ void fma2(unsigned long long& d, unsigned long long a, unsigned long long b) {
    asm("fma.rn.f32x2 %0, %1, %2, %0;" : "+l"(d) : "l"(a), "l"(b));
}
__device__ __forceinline__ float2 upk(unsigned long long v) {
    float lo, hi;
    asm("mov.b64 {%0, %1}, %2;" : "=f"(lo), "=f"(hi) : "l"(v));
    return make_float2(lo, hi);
}

// ---------------- generic tiled SGEMM with f32x2 FMA ----------------
// C[m,n] = act(sum_k A[m,k]*W[n,k] + b1[n] (+ b2[n])). A:[M,K], W:[N,K] row-major.
#define BM 64
#define BN 64
#define BK 16

template<bool RELU>
__global__ void sgemm_bias(const float* __restrict__ A, const float* __restrict__ W,
                           const float* __restrict__ bias1, const float* __restrict__ bias2,
                           float* __restrict__ C, int M, int N, int K) {
    __shared__ float As[BK][BM + 4];
    __shared__ float Ws[BK][BN + 4];

    const int tid = threadIdx.x;
    const int tx = tid & 15;
    const int ty = tid >> 4;
    const int m0 = blockIdx.y * BM;
    const int n0 = blockIdx.x * BN;

    const int lrow = tid >> 2;
    const int lkq  = (tid & 3) * 4;

    unsigned long long acc01[4] = {};   // (C[i][tx*4+0], C[i][tx*4+1])
    unsigned long long acc23[4] = {};   // (C[i][tx*4+2], C[i][tx*4+3])

    for (int k0 = 0; k0 < K; k0 += BK) {
        float4 av = *(const float4*)&A[(size_t)(m0 + lrow) * K + k0 + lkq];
        float4 wv = *(const float4*)&W[(size_t)(n0 + lrow) * K + k0 + lkq];
        As[lkq + 0][lrow] = av.x; As[lkq + 1][lrow] = av.y;
        As[lkq + 2][lrow] = av.z; As[lkq + 3][lrow] = av.w;
        Ws[lkq + 0][lrow] = wv.x; Ws[lkq + 1][lrow] = wv.y;
        Ws[lkq + 2][lrow] = wv.z; Ws[lkq + 3][lrow] = wv.w;
        __syncthreads();

        #pragma unroll
        for (int kk = 0; kk < BK; kk++) {
            float4 a4 = *(const float4*)&As[kk][ty * 4];
            float4 w4 = *(const float4*)&Ws[kk][tx * 4];
            unsigned long long w01 = pk2(w4.x, w4.y);
            unsigned long long w23 = pk2(w4.z, w4.w);
            float am[4] = {a4.x, a4.y, a4.z, a4.w};
            #pragma unroll
            for (int i = 0; i < 4; i++) {
                unsigned long long ai = pk2(am[i], am[i]);
                fma2(acc01[i], ai, w01);
                fma2(acc23[i], ai, w23);
            }
        }
        __syncthreads();
    }

    float4 bv = *(const float4*)&bias1[n0 + tx * 4];
    if (bias2) {
        float4 b2 = *(const float4*)&bias2[n0 + tx * 4];
        bv.x += b2.x; bv.y += b2.y; bv.z += b2.z; bv.w += b2.w;
    }

    #pragma unroll
    for (int i = 0; i < 4; i++) {
        float2 p01 = upk(acc01[i]);
        float2 p23 = upk(acc23[i]);
        float4 o;
        o.x = p01.x + bv.x; o.y = p01.y + bv.y;
        o.z = p23.x + bv.z; o.w = p23.y + bv.w;
        if (RELU) {
            o.x = fmaxf(o.x, 0.0f); o.y = fmaxf(o.y, 0.0f);
            o.z = fmaxf(o.z, 0.0f); o.w = fmaxf(o.w, 0.0f);
        }
        *(float4*)&C[(size_t)(m0 + ty * 4 + i) * N + n0 + tx * 4] = o;
    }
}

// ---------------- grid-wide barrier (accumulating counter) ----------------
__device__ __forceinline__ void grid_bar(int tid) {
    __syncthreads();
    if (tid == 0) {
        __threadfence();
        unsigned tk = atomicAdd(&g_bar, 1u);
        unsigned target = (tk / NBLK + 1u) * NBLK;
        while (*((volatile unsigned*)&g_bar) < target) __nanosleep(32);
    }
    __syncthreads();
}

// ---------------- persistent LSTM recurrence ----------------
// 128 blocks x 256 threads. Block owns 8 hidden units; warp w -> unit j, lane -> batch.
// Whh slice cached in SMEM (128KB). c-state in registers. h double-buffered in global.
// SMEM: ws [8][4][1024] f32 (131072B) + htc [2][32][32] float4 (32768B) = 163840B.
__global__ void __launch_bounds__(TPB, 1)
lstm_persist(const float* __restrict__ Whh, const float* __restrict__ xg,
             float* __restrict__ hA, float* __restrict__ hB, float* __restrict__ hs) {
    extern __shared__ float sm[];
    float* ws = sm;                                  // [warp][gate][k]
    float4* htc = (float4*)(sm + 8 * 4 * 1024);      // [buf][kgrp][b]

    const int tid  = threadIdx.x;
    const int lane = tid & 31;       // batch
    const int w    = tid >> 5;       // hidden unit within block
    const int j    = blockIdx.x * 8 + w;

    // cache Whh rows for our 4 gates of unit j
    #pragma unroll
    for (int g = 0; g < 4; g++) {
        const float4* src = (const float4*)(Whh + (size_t)(g * NHID + j) * NHID);
        float4* dst = (float4*)(ws + (w * 4 + g) * 1024);
        #pragma unroll
        for (int q = 0; q < 8; q++) dst[lane + q * 32] = src[lane + q * 32];
    }

    // zero initial h (our slice); c lives in a register
    hA[lane * NHID + j] = 0.0f;
    float c = 0.0f;

    grid_bar(tid);   // all zeros + weight caches in place

    const int sb = tid & 31;     // staging: batch
    const int sk = tid >> 5;     // staging: kgrp base (0..7)
    const float* wsw = ws + (w * 4) * 1024;

    for (int t = 0; t < T_; t++) {
        const float* hin = (t & 1) ? hB : hA;
        float*       hot = (t & 1) ? hA : hB;

        // prefetch gate biases for this step (independent of h)
        const float* xr = xg + ((size_t)lane * T_ + t) * G4;
        float xi  = __ldg(xr + 0 * NHID + j);
        float xf  = __ldg(xr + 1 * NHID + j);
        float xgv = __ldg(xr + 2 * NHID + j);
        float xo  = __ldg(xr + 3 * NHID + j);

        unsigned long long acc[4][2] = {};

        // prefetch chunk 0 of h into registers (L2-only: L1 is stale across SMs)
        float4 v[4];
        {
            const float4* src = (const float4*)(hin + sb * NHID);
            #pragma unroll
            for (int it = 0; it < 4; it++) v[it] = __ldcg(src + sk + it * 8);
        }

        for (int ch = 0; ch < 8; ch++) {
            const int buf = ch & 1;
            float4* hb = htc + buf * 1024;   // [32][32]
            // stage (coalesced, conflict-free: consecutive lanes -> consecutive b)
            #pragma unroll
            for (int it = 0; it < 4; it++) hb[(sk + it * 8) * 32 + sb] = v[it];
            __syncthreads();
            // prefetch next chunk while computing this one
            if (ch < 7) {
                const float4* src = (const float4*)(hin + sb * NHID + (ch + 1) * KC);
                #pragma unroll
                for (int it = 0; it < 4; it++) v[it] = __ldcg(src + sk + it * 8);
            }
            const float* wc = wsw + ch * KC;
            #pragma unroll
            for (int kg = 0; kg < 32; kg++) {
                float4 hv = hb[kg * 32 + lane];
                unsigned long long h01 = pk2(hv.x, hv.y);
                unsigned long long h23 = pk2(hv.z, hv.w);
                #pragma unroll
                for (int g = 0; g < 4; g++) {
                    float4 wv = *(const float4*)(wc + g * 1024 + kg * 4);
                    fma2(acc[g][0], pk2(wv.x, wv.y), h01);
                    fma2(acc[g][1], pk2(wv.z, wv.w), h23);
                }
            }
            __syncthreads();
        }

        // reduce packed accumulators
        float s[4];
        #pragma unroll
        for (int g = 0; g < 4; g++) {
            float2 p0 = upk(acc[g][0]);
            float2 p1 = upk(acc[g][1]);
            s[g] = (p0.x + p0.y) + (p1.x + p1.y);
        }

        float gi = s[0] + xi;
        float gf = s[1] + xf;
        float gg = s[2] + xgv;
        float go = s[3] + xo;

        float si = 1.0f / (1.0f + expf(-gi));
        float sf = 1.0f / (1.0f + expf(-gf));
        float so = 1.0f / (1.0f + expf(-go));

        c = sf * c + si * tanhf(gg);
        float h = so * tanhf(c);

        hot[lane * NHID + j] = h;
        hs[((size_t)lane * T_ + t) * NHID + j] = h;

        grid_bar(tid);
    }
}

// ---------------- softmax over last dim (64) in place ----------------
__global__ void softmax64(float* __restrict__ logits) {
    const int row  = blockIdx.x * 4 + (threadIdx.x >> 5);
    const int lane = threadIdx.x & 31;
    float* p = logits + (size_t)row * NPOL;
    float v0 = p[lane], v1 = p[lane + 32];
    float m = fmaxf(v0, v1);
    #pragma unroll
    for (int off = 16; off > 0; off >>= 1)
        m = fmaxf(m, __shfl_xor_sync(0xffffffffu, m, off));
    float e0 = expf(v0 - m), e1 = expf(v1 - m);
    float sden = e0 + e1;
    #pragma unroll
    for (int off = 16; off > 0; off >>= 1)
        sden += __shfl_xor_sync(0xffffffffu, sden, off);
    float inv = 1.0f / sden;
    p[lane] = e0 * inv;
    p[lane + 32] = e1 * inv;
}

// ---------------- value head: out[m] = dot(V[m,:512], w) + b[0] ----------------
__global__ void matvec_val(const float* __restrict__ V, const float* __restrict__ w,
                           const float* __restrict__ bias, float* __restrict__ out) {
    const int row  = blockIdx.x * 8 + (threadIdx.x >> 5);
    const int lane = threadIdx.x & 31;
    const float* vr = V + (size_t)row * ACTH;
    float s = 0.0f;
    #pragma unroll
    for (int q = 0; q < 4; q++) {
        int k = q * 128 + lane * 4;
        float4 a = *(const float4*)&vr[k];
        float4 b = *(const float4*)&w[k];
        s = fmaf(a.x, b.x, s); s = fmaf(a.y, b.y, s);
        s = fmaf(a.z, b.z, s); s = fmaf(a.w, b.w, s);
    }
    #pragma unroll
    for (int off = 16; off > 0; off >>= 1)
        s += __shfl_xor_sync(0xffffffffu, s, off);
    if (lane == 0) out[row] = s + bias[0];
}

// ---------------- launch ----------------
extern "C" void kernel_launch(void* const* d_in, const int* in_sizes, int n_in,
                              void* d_out, int out_size) {
    const float* x        = (const float*)d_in[0];
    const float* pre_W0   = (const float*)d_in[1];
    const float* pre_b0   = (const float*)d_in[2];
    const float* pre_W1   = (const float*)d_in[3];
    const float* pre_b1   = (const float*)d_in[4];
    const float* w_ih     = (const float*)d_in[5];
    const float* w_hh     = (const float*)d_in[6];
    const float* b_ih     = (const float*)d_in[7];
    const float* b_hh     = (const float*)d_in[8];
    const float* act_W0   = (const float*)d_in[9];
    const float* act_b0   = (const float*)d_in[10];
    const float* act_W1   = (const float*)d_in[11];
    const float* act_b1   = (const float*)d_in[12];
    const float* val_W0   = (const float*)d_in[13];
    const float* val_b0   = (const float*)d_in[14];
    const float* val_W1   = (const float*)d_in[15];
    const float* val_b1   = (const float*)d_in[16];

    float* out_probs = (float*)d_out;
    float* out_value = (float*)d_out + (size_t)MTOT * NPOL;

    float *pH, *pU, *pXG, *pHS, *pA, *pV, *pHA, *pHB;
    cudaGetSymbolAddress((void**)&pH,  g_h);
    cudaGetSymbolAddress((void**)&pU,  g_u);
    cudaGetSymbolAddress((void**)&pXG, g_xg);
    cudaGetSymbolAddress((void**)&pHS, g_hs);
    cudaGetSymbolAddress((void**)&pA,  g_a);
    cudaGetSymbolAddress((void**)&pV,  g_v);
    cudaGetSymbolAddress((void**)&pHA, g_hstA);
    cudaGetSymbolAddress((void**)&pHB, g_hstB);

    const int SMEM_BYTES = 8 * 4 * 1024 * 4 + 2 * 32 * 32 * 16;  // 163840
    cudaFuncSetAttribute(lstm_persist, cudaFuncAttributeMaxDynamicSharedMemorySize, SMEM_BYTES);

    // reset barrier counter for this replay
    reset_bar<<<1, 1>>>();

    // pre_dnn
    sgemm_bias<true ><<<dim3(PRE_ / BN, MTOT / BM), 256>>>(x,  pre_W0, pre_b0, nullptr, pH, MTOT, PRE_, IN_);
    sgemm_bias<false><<<dim3(LH_  / BN, MTOT / BM), 256>>>(pH, pre_W1, pre_b1, nullptr, pU, MTOT, LH_, PRE_);

    // input contribution to gates (+ both biases)
    sgemm_bias<false><<<dim3(G4 / BN, MTOT / BM), 256>>>(pU, w_ih, b_ih, b_hh, pXG, MTOT, G4, LH_);

    // persistent recurrence (one launch for all 512 steps)
    lstm_persist<<<NBLK, TPB, SMEM_BYTES>>>(w_hh, pXG, pHA, pHB, pHS);

    // policy head
    sgemm_bias<true ><<<dim3(ACTH / BN, MTOT / BM), 256>>>(pHS, act_W0, act_b0, nullptr, pA, MTOT, ACTH, NHID);
    sgemm_bias<false><<<dim3(NPOL / BN, MTOT / BM), 256>>>(pA, act_W1, act_b1, nullptr, out_probs, MTOT, NPOL, ACTH);
    softmax64<<<MTOT / 4, 128>>>(out_probs);

    // value head
    sgemm_bias<true ><<<dim3(ACTH / BN, MTOT / BM), 256>>>(pHS, val_W0, val_b0, nullptr, pV, MTOT, ACTH, NHID);
    matvec_val<<<MTOT / 8, 256>>>(pV, val_W1, val_b1, out_value);
}

// round 8
// speedup vs baseline: 3.4236x; 1.2841x over previous
#include <cuda_runtime.h>
#include <math.h>

#define B_    32
#define T_    512
#define IN_   256
#define PRE_  512
#define LH_   512
#define NHID  1024
#define ACTH  512
#define NPOL  64
#define MTOT  (B_ * T_)      // 16384
#define G4    (4 * NHID)     // 4096

#define NBLK  128            // persistent blocks (<=148 SMs, co-resident)
#define RTPB  256

// ---------------- scratch (device globals; no allocation allowed) ----------------
__device__ float g_h [(size_t)MTOT * PRE_];
__device__ float g_u [(size_t)MTOT * LH_];
__device__ float g_xg[(size_t)MTOT * G4];
__device__ float g_hs[(size_t)MTOT * NHID];
__device__ float g_a [(size_t)MTOT * ACTH];
__device__ float g_v [(size_t)MTOT * ACTH];
__device__ float g_hstA[B_ * NHID];
__device__ float g_hstB[B_ * NHID];
__device__ unsigned g_bar;

__global__ void reset_bar() { g_bar = 0u; }

// ---------------- packed f32x2 helpers ----------------
__device__ __forceinline__ unsigned long long pk2(float lo, float hi) {
    unsigned long long r;
    asm("mov.b64 %0, {%1, %2};" : "=l"(r) : "f"(lo), "f"(hi));
    return r;
}
__device__ __forceinline__ void fma2(unsigned long long& d, unsigned long long a, unsigned long long b) {
    asm("fma.rn.f32x2 %0, %1, %2, %0;" : "+l"(d) : "l"(a), "l"(b));
}
__device__ __forceinline__ float2 upk(unsigned long long v) {
    float lo, hi;
    asm("mov.b64 {%0, %1}, %2;" : "=f"(lo), "=f"(hi) : "l"(v));
    return make_float2(lo, hi);
}

// ---------------- feedforward SGEMM: 128x64 tile, 8x4 micro, f32x2 ----------------
// C[m,n] = act(sum_k A[m,k]*W[n,k] + b1[n] (+ b2[n])). A:[M,K], W:[N,K] row-major.
#define BK  16
#define BM2 128
#define BN2 64

template<bool RELU>
__global__ void __launch_bounds__(256)
sgemm128(const float* __restrict__ A, const float* __restrict__ W,
         const float* __restrict__ bias1, const float* __restrict__ bias2,
         float* __restrict__ C, int M, int N, int K)
{
    __shared__ float As[BK][BM2 + 4];
    __shared__ float Ws[BK][BN2 + 4];

    const int tid = threadIdx.x;
    const int tx = tid & 15;          // n micro (4 cols)
    const int ty = tid >> 4;          // m micro (8 rows)
    const int m0 = blockIdx.y * BM2;
    const int n0 = blockIdx.x * BN2;

    const int arow = tid >> 1, akq = (tid & 1) * 8;
    const int wrow = tid >> 2, wkq = (tid & 3) * 4;

    unsigned long long acc[4][4] = {};   // [m-pair p -> rows (2p,2p+1)][n col]

    for (int k0 = 0; k0 < K; k0 += BK) {
        float4 a0 = *(const float4*)&A[(size_t)(m0 + arow) * K + k0 + akq];
        float4 a1 = *(const float4*)&A[(size_t)(m0 + arow) * K + k0 + akq + 4];
        float4 wv = *(const float4*)&W[(size_t)(n0 + wrow) * K + k0 + wkq];
        As[akq + 0][arow] = a0.x; As[akq + 1][arow] = a0.y;
        As[akq + 2][arow] = a0.z; As[akq + 3][arow] = a0.w;
        As[akq + 4][arow] = a1.x; As[akq + 5][arow] = a1.y;
        As[akq + 6][arow] = a1.z; As[akq + 7][arow] = a1.w;
        Ws[wkq + 0][wrow] = wv.x; Ws[wkq + 1][wrow] = wv.y;
        Ws[wkq + 2][wrow] = wv.z; Ws[wkq + 3][wrow] = wv.w;
        __syncthreads();

        #pragma unroll
        for (int kk = 0; kk < BK; kk++) {
            float4 am0 = *(const float4*)&As[kk][ty * 8];
            float4 am1 = *(const float4*)&As[kk][ty * 8 + 4];
            float4 w4  = *(const float4*)&Ws[kk][tx * 4];
            unsigned long long ap[4] = { pk2(am0.x, am0.y), pk2(am0.z, am0.w),
                                         pk2(am1.x, am1.y), pk2(am1.z, am1.w) };
            float wn[4] = {w4.x, w4.y, w4.z, w4.w};
            #pragma unroll
            for (int j = 0; j < 4; j++) {
                unsigned long long wd = pk2(wn[j], wn[j]);
                #pragma unroll
                for (int p = 0; p < 4; p++) fma2(acc[p][j], ap[p], wd);
            }
        }
        __syncthreads();
    }

    float4 bv = *(const float4*)&bias1[n0 + tx * 4];
    if (bias2) {
        float4 b2 = *(const float4*)&bias2[n0 + tx * 4];
        bv.x += b2.x; bv.y += b2.y; bv.z += b2.z; bv.w += b2.w;
    }
    float bn[4] = {bv.x, bv.y, bv.z, bv.w};

    #pragma unroll
    for (int p = 0; p < 4; p++) {
        float2 u0 = upk(acc[p][0]), u1 = upk(acc[p][1]);
        float2 u2 = upk(acc[p][2]), u3 = upk(acc[p][3]);
        float4 lo = {u0.x + bn[0], u1.x + bn[1], u2.x + bn[2], u3.x + bn[3]};
        float4 hi = {u0.y + bn[0], u1.y + bn[1], u2.y + bn[2], u3.y + bn[3]};
        if (RELU) {
            lo.x = fmaxf(lo.x, 0.f); lo.y = fmaxf(lo.y, 0.f);
            lo.z = fmaxf(lo.z, 0.f); lo.w = fmaxf(lo.w, 0.f);
            hi.x = fmaxf(hi.x, 0.f); hi.y = fmaxf(hi.y, 0.f);
            hi.z = fmaxf(hi.z, 0.f); hi.w = fmaxf(hi.w, 0.f);
        }
        *(float4*)&C[(size_t)(m0 + ty * 8 + 2 * p)     * N + n0 + tx * 4] = lo;
        *(float4*)&C[(size_t)(m0 + ty * 8 + 2 * p + 1) * N + n0 + tx * 4] = hi;
    }
}

// ---------------- grid-wide barrier (accumulating counter) ----------------
__device__ __forceinline__ void grid_bar(int tid) {
    __syncthreads();
    if (tid == 0) {
        __threadfence();
        unsigned tk = atomicAdd(&g_bar, 1u);
        unsigned target = (tk / NBLK + 1u) * NBLK;
        while (*((volatile unsigned*)&g_bar) < target) __nanosleep(16);
    }
    __syncthreads();
}

// ---------------- persistent LSTM recurrence ----------------
// 128 blocks x 256 threads (8 warps). Block owns 8 units = 32 gate-rows.
// Warp group rg = w&3 owns 2 units (8 rows); warps rg and rg+4 split K (512 each).
// Weights (128KB) SMEM-resident; h chunks (128 float) double-buffered per K-half;
// c-state in registers; cross-half reduce via 4KB SMEM.
// SMEM floats: ws 4*8*1024 = 32768 | htc 2*2*32*132 = 16896 | red 4*8*32 = 1024
#define WS_F   (4 * 8 * 1024)
#define HTC_F  (2 * 2 * 32 * 132)
#define RED_F  (4 * 8 * 32)
#define RSMEM_BYTES ((WS_F + HTC_F + RED_F) * 4)

__global__ void __launch_bounds__(RTPB, 1)
lstm_persist(const float* __restrict__ Whh, const float* __restrict__ xg,
             float* __restrict__ hA, float* __restrict__ hB, float* __restrict__ hs)
{
    extern __shared__ float sm[];
    float* ws  = sm;                     // [rg][r][1024]
    float* htc = sm + WS_F;              // [half][buf][32 b][132]
    float* red = sm + WS_F + HTC_F;      // [rg][r][32 b]

    const int tid  = threadIdx.x;
    const int lane = tid & 31;           // batch
    const int w    = tid >> 5;           // 0..7
    const int rg   = w & 3;              // row group (2 units)
    const int half = w >> 2;             // K half
    const int bid  = blockIdx.x;

    // ---- load weights: warp w loads flat rows w*4 .. w*4+3 (coalesced) ----
    #pragma unroll
    for (int rr = 0; rr < 4; rr++) {
        int r32  = w * 4 + rr;           // 0..31
        int grp  = r32 >> 3;
        int r    = r32 & 7;              // r: unit_off = r>>2, gate = r&3
        int unit = bid * 8 + grp * 2 + (r >> 2);
        int gate = r & 3;
        const float4* src = (const float4*)(Whh + ((size_t)gate * NHID + unit) * NHID);
        float4* dst = (float4*)(ws + (size_t)(grp * 8 + r) * 1024);
        #pragma unroll
        for (int q = 0; q < 8; q++) dst[lane + q * 32] = src[lane + q * 32];
    }

    const int u0 = bid * 8 + rg * 2;
    if (w < 4) {
        __stcg(&hA[lane * NHID + u0],     0.0f);
        __stcg(&hA[lane * NHID + u0 + 1], 0.0f);
    }

    grid_bar(tid);

    // staging: each K-half staged by its own 128 threads
    const int st = tid & 127;
    const int sb = st >> 2;              // batch 0..31
    const int sk = st & 3;               // kg base
    const int myhalf = tid >> 7;
    float* myhtc = htc + myhalf * (2 * 32 * 132);

    const float* wrow0 = ws + (size_t)(rg * 8) * 1024 + half * 512;

    float c0 = 0.f, c1 = 0.f;

    for (int t = 0; t < T_; t++) {
        const float* hin = (t & 1) ? hB : hA;
        float*       hot = (t & 1) ? hA : hB;

        // gate biases for this step (only needed by warps 0..3)
        float xv[8];
        if (w < 4) {
            const float* xr = xg + ((size_t)lane * T_ + t) * G4;
            #pragma unroll
            for (int g = 0; g < 4; g++) {
                xv[g]     = __ldg(xr + g * NHID + u0);
                xv[4 + g] = __ldg(xr + g * NHID + u0 + 1);
            }
        }

        // stage chunk 0 of my half
        {
            const float4* src = (const float4*)(hin + sb * NHID + myhalf * 512);
            float* dstb = myhtc + sb * 132;
            #pragma unroll
            for (int it = 0; it < 8; it++) {
                float4 v = __ldcg(src + sk + 4 * it);
                *(float4*)(dstb + (sk + 4 * it) * 4) = v;
            }
        }
        __syncthreads();

        unsigned long long acc[8][2] = {};

        for (int chl = 0; chl < 4; chl++) {
            const int buf = chl & 1;
            // prefetch next chunk into registers (overlaps with compute)
            float4 v[8];
            if (chl < 3) {
                const float4* src = (const float4*)(hin + sb * NHID + myhalf * 512 + (chl + 1) * 128);
                #pragma unroll
                for (int it = 0; it < 8; it++) v[it] = __ldcg(src + sk + 4 * it);
            }
            // compute on current buffer
            const float* hb = myhtc + buf * (32 * 132) + lane * 132;
            const float* wc = wrow0 + chl * 128;
            #pragma unroll 4
            for (int kg = 0; kg < 32; kg++) {
                float4 hv = *(const float4*)(hb + kg * 4);
                unsigned long long h01 = pk2(hv.x, hv.y);
                unsigned long long h23 = pk2(hv.z, hv.w);
                #pragma unroll
                for (int r = 0; r < 8; r++) {
                    float4 wv = *(const float4*)(wc + r * 1024 + kg * 4);
                    fma2(acc[r][0], pk2(wv.x, wv.y), h01);
                    fma2(acc[r][1], pk2(wv.z, wv.w), h23);
                }
            }
            // commit next chunk to the other buffer
            if (chl < 3) {
                float* dstb = myhtc + (buf ^ 1) * (32 * 132) + sb * 132;
                #pragma unroll
                for (int it = 0; it < 8; it++)
                    *(float4*)(dstb + (sk + 4 * it) * 4) = v[it];
            }
            __syncthreads();
        }

        // horizontal sums of packed accumulators
        float s[8];
        #pragma unroll
        for (int r = 0; r < 8; r++) {
            float2 p0 = upk(acc[r][0]);
            float2 p1 = upk(acc[r][1]);
            s[r] = (p0.x + p0.y) + (p1.x + p1.y);
        }
        // cross-half reduction
        if (w >= 4) {
            float* rb = red + (size_t)(rg * 8) * 32;
            #pragma unroll
            for (int r = 0; r < 8; r++) rb[r * 32 + lane] = s[r];
        }
        __syncthreads();
        if (w < 4) {
            const float* rb = red + (size_t)(rg * 8) * 32;
            #pragma unroll
            for (int r = 0; r < 8; r++) s[r] += rb[r * 32 + lane];

            // unit 0: rows 0..3 = gates i,f,g,o ; unit 1: rows 4..7
            float gi0 = s[0] + xv[0], gf0 = s[1] + xv[1], gg0 = s[2] + xv[2], go0 = s[3] + xv[3];
            float gi1 = s[4] + xv[4], gf1 = s[5] + xv[5], gg1 = s[6] + xv[6], go1 = s[7] + xv[7];

            float si0 = 1.0f / (1.0f + expf(-gi0));
            float sf0 = 1.0f / (1.0f + expf(-gf0));
            float so0 = 1.0f / (1.0f + expf(-go0));
            float si1 = 1.0f / (1.0f + expf(-gi1));
            float sf1 = 1.0f / (1.0f + expf(-gf1));
            float so1 = 1.0f / (1.0f + expf(-go1));

            c0 = sf0 * c0 + si0 * tanhf(gg0);
            c1 = sf1 * c1 + si1 * tanhf(gg1);
            float h0 = so0 * tanhf(c0);
            float h1 = so1 * tanhf(c1);

            __stcg(&hot[lane * NHID + u0],     h0);
            __stcg(&hot[lane * NHID + u0 + 1], h1);
            hs[((size_t)lane * T_ + t) * NHID + u0]     = h0;
            hs[((size_t)lane * T_ + t) * NHID + u0 + 1] = h1;
        }

        grid_bar(tid);
    }
}

// ---------------- softmax over last dim (64) in place ----------------
__global__ void softmax64(float* __restrict__ logits) {
    const int row  = blockIdx.x * 4 + (threadIdx.x >> 5);
    const int lane = threadIdx.x & 31;
    float* p = logits + (size_t)row * NPOL;
    float v0 = p[lane], v1 = p[lane + 32];
    float m = fmaxf(v0, v1);
    #pragma unroll
    for (int off = 16; off > 0; off >>= 1)
        m = fmaxf(m, __shfl_xor_sync(0xffffffffu, m, off));
    float e0 = expf(v0 - m), e1 = expf(v1 - m);
    float sden = e0 + e1;
    #pragma unroll
    for (int off = 16; off > 0; off >>= 1)
        sden += __shfl_xor_sync(0xffffffffu, sden, off);
    float inv = 1.0f / sden;
    p[lane] = e0 * inv;
    p[lane + 32] = e1 * inv;
}

// ---------------- value head: out[m] = dot(V[m,:512], w) + b[0] ----------------
__global__ void matvec_val(const float* __restrict__ V, const float* __restrict__ w,
                           const float* __restrict__ bias, float* __restrict__ out) {
    const int row  = blockIdx.x * 8 + (threadIdx.x >> 5);
    const int lane = threadIdx.x & 31;
    const float* vr = V + (size_t)row * ACTH;
    float s = 0.0f;
    #pragma unroll
    for (int q = 0; q < 4; q++) {
        int k = q * 128 + lane * 4;
        float4 a = *(const float4*)&vr[k];
        float4 b = *(const float4*)&w[k];
        s = fmaf(a.x, b.x, s); s = fmaf(a.y, b.y, s);
        s = fmaf(a.z, b.z, s); s = fmaf(a.w, b.w, s);
    }
    #pragma unroll
    for (int off = 16; off > 0; off >>= 1)
        s += __shfl_xor_sync(0xffffffffu, s, off);
    if (lane == 0) out[row] = s + bias[0];
}

// ---------------- launch ----------------
extern "C" void kernel_launch(void* const* d_in, const int* in_sizes, int n_in,
                              void* d_out, int out_size) {
    const float* x        = (const float*)d_in[0];
    const float* pre_W0   = (const float*)d_in[1];
    const float* pre_b0   = (const float*)d_in[2];
    const float* pre_W1   = (const float*)d_in[3];
    const float* pre_b1   = (const float*)d_in[4];
    const float* w_ih     = (const float*)d_in[5];
    const float* w_hh     = (const float*)d_in[6];
    const float* b_ih     = (const float*)d_in[7];
    const float* b_hh     = (const float*)d_in[8];
    const float* act_W0   = (const float*)d_in[9];
    const float* act_b0   = (const float*)d_in[10];
    const float* act_W1   = (const float*)d_in[11];
    const float* act_b1   = (const float*)d_in[12];
    const float* val_W0   = (const float*)d_in[13];
    const float* val_b0   = (const float*)d_in[14];
    const float* val_W1   = (const float*)d_in[15];
    const float* val_b1   = (const float*)d_in[16];

    float* out_probs = (float*)d_out;
    float* out_value = (float*)d_out + (size_t)MTOT * NPOL;

    float *pH, *pU, *pXG, *pHS, *pA, *pV, *pHA, *pHB;
    cudaGetSymbolAddress((void**)&pH,  g_h);
    cudaGetSymbolAddress((void**)&pU,  g_u);
    cudaGetSymbolAddress((void**)&pXG, g_xg);
    cudaGetSymbolAddress((void**)&pHS, g_hs);
    cudaGetSymbolAddress((void**)&pA,  g_a);
    cudaGetSymbolAddress((void**)&pV,  g_v);
    cudaGetSymbolAddress((void**)&pHA, g_hstA);
    cudaGetSymbolAddress((void**)&pHB, g_hstB);

    cudaFuncSetAttribute(lstm_persist, cudaFuncAttributeMaxDynamicSharedMemorySize, RSMEM_BYTES);

    reset_bar<<<1, 1>>>();

    // pre_dnn
    sgemm128<true ><<<dim3(PRE_ / BN2, MTOT / BM2), 256>>>(x,  pre_W0, pre_b0, nullptr, pH, MTOT, PRE_, IN_);
    sgemm128<false><<<dim3(LH_  / BN2, MTOT / BM2), 256>>>(pH, pre_W1, pre_b1, nullptr, pU, MTOT, LH_, PRE_);

    // input contribution to gates (+ both biases)
    sgemm128<false><<<dim3(G4 / BN2, MTOT / BM2), 256>>>(pU, w_ih, b_ih, b_hh, pXG, MTOT, G4, LH_);

    // persistent recurrence (one launch for all 512 steps)
    lstm_persist<<<NBLK, RTPB, RSMEM_BYTES>>>(w_hh, pXG, pHA, pHB, pHS);

    // policy head
    sgemm128<true ><<<dim3(ACTH / BN2, MTOT / BM2), 256>>>(pHS, act_W0, act_b0, nullptr, pA, MTOT, ACTH, NHID);
    sgemm128<false><<<dim3(NPOL / BN2, MTOT / BM2), 256>>>(pA, act_W1, act_b1, nullptr, out_probs, MTOT, NPOL, ACTH);
    softmax64<<<MTOT / 4, 128>>>(out_probs);

    // value head
    sgemm128<true ><<<dim3(ACTH / BN2, MTOT / BM2), 256>>>(pHS, val_W0, val_b0, nullptr, pV, MTOT, ACTH, NHID);
    matvec_val<<<MTOT / 8, 256>>>(pV, val_W1, val_b1, out_value);
}

// round 9
// speedup vs baseline: 3.4268x; 1.0009x over previous
#include <cuda_runtime.h>
#include <math.h>

#define B_    32
#define T_    512
#define IN_   256
#define PRE_  512
#define LH_   512
#define NHID  1024
#define ACTH  512
#define NPOL  64
#define MTOT  (B_ * T_)      // 16384
#define G4    (4 * NHID)     // 4096

#define NBLK  128            // persistent blocks (<=148 SMs, co-resident)
#define RTPB  256

// ---------------- scratch (device globals; no allocation allowed) ----------------
__device__ float g_h [(size_t)MTOT * PRE_];
__device__ float g_u [(size_t)MTOT * LH_];
__device__ float g_xg[(size_t)MTOT * G4];
__device__ float g_hs[(size_t)MTOT * NHID];
__device__ float g_a [(size_t)MTOT * ACTH];
__device__ float g_v [(size_t)MTOT * ACTH];
__device__ float g_hstA[B_ * NHID];
__device__ float g_hstB[B_ * NHID];
__device__ unsigned g_bar;

__global__ void reset_bar() { g_bar = 0u; }

// ---------------- packed f32x2 helpers ----------------
__device__ __forceinline__ unsigned long long pk2(float lo, float hi) {
    unsigned long long r;
    asm("mov.b64 %0, {%1, %2};" : "=l"(r) : "f"(lo), "f"(hi));
    return r;
}
__device__ __forceinline__ void fma2(unsigned long long& d, unsigned long long a, unsigned long long b) {
    asm("fma.rn.f32x2 %0, %1, %2, %0;" : "+l"(d) : "l"(a), "l"(b));
}
__device__ __forceinline__ float2 upk(unsigned long long v) {
    float lo, hi;
    asm("mov.b64 {%0, %1}, %2;" : "=f"(lo), "=f"(hi) : "l"(v));
    return make_float2(lo, hi);
}

// ---------------- feedforward SGEMM: 128x64 tile, 8x4 micro, f32x2 ----------------
// C[m,n] = act(sum_k A[m,k]*W[n,k] + b1[n] (+ b2[n])). A:[M,K], W:[N,K] row-major.
#define BK  16
#define BM2 128
#define BN2 64

template<bool RELU>
__global__ void __launch_bounds__(256)
sgemm128(const float* __restrict__ A, const float* __restrict__ W,
         const float* __restrict__ bias1, const float* __restrict__ bias2,
         float* __restrict__ C, int M, int N, int K)
{
    __shared__ float As[BK][BM2 + 4];   // row stride 132 floats = 528B (16B mult.)
    __shared__ float Ws[BK][BN2 + 4];   // row stride 68 floats = 272B (16B mult.)

    const int tid = threadIdx.x;
    const int tx = tid & 15;          // n micro (4 cols)
    const int ty = tid >> 4;          // m micro (8 rows)
    const int m0 = blockIdx.y * BM2;
    const int n0 = blockIdx.x * BN2;

    const int arow = tid >> 1, akq = (tid & 1) * 8;
    const int wrow = tid >> 2, wkq = (tid & 3) * 4;

    unsigned long long acc[4][4] = {};   // [m-pair p -> rows (2p,2p+1)][n col]

    for (int k0 = 0; k0 < K; k0 += BK) {
        float4 a0 = *(const float4*)&A[(size_t)(m0 + arow) * K + k0 + akq];
        float4 a1 = *(const float4*)&A[(size_t)(m0 + arow) * K + k0 + akq + 4];
        float4 wv = *(const float4*)&W[(size_t)(n0 + wrow) * K + k0 + wkq];
        As[akq + 0][arow] = a0.x; As[akq + 1][arow] = a0.y;
        As[akq + 2][arow] = a0.z; As[akq + 3][arow] = a0.w;
        As[akq + 4][arow] = a1.x; As[akq + 5][arow] = a1.y;
        As[akq + 6][arow] = a1.z; As[akq + 7][arow] = a1.w;
        Ws[wkq + 0][wrow] = wv.x; Ws[wkq + 1][wrow] = wv.y;
        Ws[wkq + 2][wrow] = wv.z; Ws[wkq + 3][wrow] = wv.w;
        __syncthreads();

        #pragma unroll
        for (int kk = 0; kk < BK; kk++) {
            // a m-pairs arrive as aligned b64 halves of LDS.128 (no pack MOVs)
            const ulonglong2* ap2 = (const ulonglong2*)&As[kk][ty * 8];
            ulonglong2 aA = ap2[0];
            ulonglong2 aB = ap2[1];
            unsigned long long ap[4] = { aA.x, aA.y, aB.x, aB.y };
            float4 w4 = *(const float4*)&Ws[kk][tx * 4];
            float wn[4] = {w4.x, w4.y, w4.z, w4.w};
            #pragma unroll
            for (int j = 0; j < 4; j++) {
                unsigned long long wd = pk2(wn[j], wn[j]);   // dup pack (4/kk)
                #pragma unroll
                for (int p = 0; p < 4; p++) fma2(acc[p][j], ap[p], wd);
            }
        }
        __syncthreads();
    }

    float4 bv = *(const float4*)&bias1[n0 + tx * 4];
    if (bias2) {
        float4 b2 = *(const float4*)&bias2[n0 + tx * 4];
        bv.x += b2.x; bv.y += b2.y; bv.z += b2.z; bv.w += b2.w;
    }
    float bn[4] = {bv.x, bv.y, bv.z, bv.w};

    #pragma unroll
    for (int p = 0; p < 4; p++) {
        float2 u0 = upk(acc[p][0]), u1 = upk(acc[p][1]);
        float2 u2 = upk(acc[p][2]), u3 = upk(acc[p][3]);
        float4 lo = {u0.x + bn[0], u1.x + bn[1], u2.x + bn[2], u3.x + bn[3]};
        float4 hi = {u0.y + bn[0], u1.y + bn[1], u2.y + bn[2], u3.y + bn[3]};
        if (RELU) {
            lo.x = fmaxf(lo.x, 0.f); lo.y = fmaxf(lo.y, 0.f);
            lo.z = fmaxf(lo.z, 0.f); lo.w = fmaxf(lo.w, 0.f);
            hi.x = fmaxf(hi.x, 0.f); hi.y = fmaxf(hi.y, 0.f);
            hi.z = fmaxf(hi.z, 0.f); hi.w = fmaxf(hi.w, 0.f);
        }
        *(float4*)&C[(size_t)(m0 + ty * 8 + 2 * p)     * N + n0 + tx * 4] = lo;
        *(float4*)&C[(size_t)(m0 + ty * 8 + 2 * p + 1) * N + n0 + tx * 4] = hi;
    }
}

// ---------------- grid-wide barrier (accumulating counter) ----------------
__device__ __forceinline__ void grid_bar(int tid) {
    __syncthreads();
    if (tid == 0) {
        __threadfence();
        unsigned tk = atomicAdd(&g_bar, 1u);
        unsigned target = (tk / NBLK + 1u) * NBLK;
        while (*((volatile unsigned*)&g_bar) < target) __nanosleep(16);
    }
    __syncthreads();
}

// ---------------- persistent LSTM recurrence ----------------
// 128 blocks x 256 threads (8 warps). Block owns 8 units = 32 gate-rows.
// Warp group rg = w&3 owns 2 units (8 rows); warps rg and rg+4 split K (512 each).
// Weights (128KB) SMEM-resident; h chunks double-buffered per K-half;
// c-state in registers; cross-half reduce via SMEM.
// SMEM floats: ws 4*8*1024 = 32768 | htc 2*2*32*132 = 16896 | red 4*8*32 = 1024
#define WS_F   (4 * 8 * 1024)
#define HTC_F  (2 * 2 * 32 * 132)
#define RED_F  (4 * 8 * 32)
#define RSMEM_BYTES ((WS_F + HTC_F + RED_F) * 4)

__global__ void __launch_bounds__(RTPB, 1)
lstm_persist(const float* __restrict__ Whh, const float* __restrict__ xg,
             float* __restrict__ hA, float* __restrict__ hB, float* __restrict__ hs)
{
    extern __shared__ float sm[];
    float* ws  = sm;                     // [rg][r][1024]
    float* htc = sm + WS_F;              // [half][buf][32 b][132]
    float* red = sm + WS_F + HTC_F;      // [rg][r][32 b]

    const int tid  = threadIdx.x;
    const int lane = tid & 31;           // batch
    const int w    = tid >> 5;           // 0..7
    const int rg   = w & 3;              // row group (2 units)
    const int half = w >> 2;             // K half
    const int bid  = blockIdx.x;

    // ---- load weights: warp w loads flat rows w*4 .. w*4+3 (coalesced) ----
    #pragma unroll
    for (int rr = 0; rr < 4; rr++) {
        int r32  = w * 4 + rr;           // 0..31
        int grp  = r32 >> 3;
        int r    = r32 & 7;              // r: unit_off = r>>2, gate = r&3
        int unit = bid * 8 + grp * 2 + (r >> 2);
        int gate = r & 3;
        const float4* src = (const float4*)(Whh + ((size_t)gate * NHID + unit) * NHID);
        float4* dst = (float4*)(ws + (size_t)(grp * 8 + r) * 1024);
        #pragma unroll
        for (int q = 0; q < 8; q++) dst[lane + q * 32] = src[lane + q * 32];
    }

    const int u0 = bid * 8 + rg * 2;
    if (w < 4) {
        __stcg(&hA[lane * NHID + u0],     0.0f);
        __stcg(&hA[lane * NHID + u0 + 1], 0.0f);
    }

    grid_bar(tid);

    // staging: each K-half staged by its own 128 threads
    const int st = tid & 127;
    const int sb = st >> 2;              // batch 0..31
    const int sk = st & 3;               // kg base
    const int myhalf = tid >> 7;
    float* myhtc = htc + myhalf * (2 * 32 * 132);

    const float* wrow0 = ws + (size_t)(rg * 8) * 1024 + half * 512;

    float c0 = 0.f, c1 = 0.f;

    for (int t = 0; t < T_; t++) {
        const float* hin = (t & 1) ? hB : hA;
        float*       hot = (t & 1) ? hA : hB;

        // gate biases for this step (only needed by warps 0..3)
        float xv[8];
        if (w < 4) {
            const float* xr = xg + ((size_t)lane * T_ + t) * G4;
            #pragma unroll
            for (int g = 0; g < 4; g++) {
                xv[g]     = __ldg(xr + g * NHID + u0);
                xv[4 + g] = __ldg(xr + g * NHID + u0 + 1);
            }
        }

        // stage chunk 0 of my half
        {
            const float4* src = (const float4*)(hin + sb * NHID + myhalf * 512);
            float* dstb = myhtc + sb * 132;
            #pragma unroll
            for (int it = 0; it < 8; it++) {
                float4 v = __ldcg(src + sk + 4 * it);
                *(float4*)(dstb + (sk + 4 * it) * 4) = v;
            }
        }
        __syncthreads();

        unsigned long long acc[8][2] = {};

        for (int chl = 0; chl < 4; chl++) {
            const int buf = chl & 1;
            // prefetch next chunk into registers (overlaps with compute)
            float4 v[8];
            if (chl < 3) {
                const float4* src = (const float4*)(hin + sb * NHID + myhalf * 512 + (chl + 1) * 128);
                #pragma unroll
                for (int it = 0; it < 8; it++) v[it] = __ldcg(src + sk + 4 * it);
            }
            // compute on current buffer — all operands read as aligned b64 pairs
            const float* hb = myhtc + buf * (32 * 132) + lane * 132;
            const float* wc = wrow0 + chl * 128;
            #pragma unroll 8
            for (int kg = 0; kg < 32; kg++) {
                ulonglong2 hv = *(const ulonglong2*)(hb + kg * 4);
                #pragma unroll
                for (int r = 0; r < 8; r++) {
                    ulonglong2 wv = *(const ulonglong2*)(wc + r * 1024 + kg * 4);
                    fma2(acc[r][0], wv.x, hv.x);
                    fma2(acc[r][1], wv.y, hv.y);
                }
            }
            // commit next chunk to the other buffer
            if (chl < 3) {
                float* dstb = myhtc + (buf ^ 1) * (32 * 132) + sb * 132;
                #pragma unroll
                for (int it = 0; it < 8; it++)
                    *(float4*)(dstb + (sk + 4 * it) * 4) = v[it];
            }
            __syncthreads();
        }

        // horizontal sums of packed accumulators
        float s[8];
        #pragma unroll
        for (int r = 0; r < 8; r++) {
            float2 p0 = upk(acc[r][0]);
            float2 p1 = upk(acc[r][1]);
            s[r] = (p0.x + p0.y) + (p1.x + p1.y);
        }
        // cross-half reduction
        if (w >= 4) {
            float* rb = red + (size_t)(rg * 8) * 32;
            #pragma unroll
            for (int r = 0; r < 8; r++) rb[r * 32 + lane] = s[r];
        }
        __syncthreads();
        if (w < 4) {
            const float* rb = red + (size_t)(rg * 8) * 32;
            #pragma unroll
            for (int r = 0; r < 8; r++) s[r] += rb[r * 32 + lane];

            // unit 0: rows 0..3 = gates i,f,g,o ; unit 1: rows 4..7
            float gi0 = s[0] + xv[0], gf0 = s[1] + xv[1], gg0 = s[2] + xv[2], go0 = s[3] + xv[3];
            float gi1 = s[4] + xv[4], gf1 = s[5] + xv[5], gg1 = s[6] + xv[6], go1 = s[7] + xv[7];

            float si0 = 1.0f / (1.0f + expf(-gi0));
            float sf0 = 1.0f / (1.0f + expf(-gf0));
            float so0 = 1.0f / (1.0f + expf(-go0));
            float si1 = 1.0f / (1.0f + expf(-gi1));
            float sf1 = 1.0f / (1.0f + expf(-gf1));
            float so1 = 1.0f / (1.0f + expf(-go1));

            c0 = sf0 * c0 + si0 * tanhf(gg0);
            c1 = sf1 * c1 + si1 * tanhf(gg1);
            float h0 = so0 * tanhf(c0);
            float h1 = so1 * tanhf(c1);

            __stcg(&hot[lane * NHID + u0],     h0);
            __stcg(&hot[lane * NHID + u0 + 1], h1);
            hs[((size_t)lane * T_ + t) * NHID + u0]     = h0;
            hs[((size_t)lane * T_ + t) * NHID + u0 + 1] = h1;
        }

        grid_bar(tid);
    }
}

// ---------------- softmax over last dim (64) in place ----------------
__global__ void softmax64(float* __restrict__ logits) {
    const int row  = blockIdx.x * 4 + (threadIdx.x >> 5);
    const int lane = threadIdx.x & 31;
    float* p = logits + (size_t)row * NPOL;
    float v0 = p[lane], v1 = p[lane + 32];
    float m = fmaxf(v0, v1);
    #pragma unroll
    for (int off = 16; off > 0; off >>= 1)
        m = fmaxf(m, __shfl_xor_sync(0xffffffffu, m, off));
    float e0 = expf(v0 - m), e1 = expf(v1 - m);
    float sden = e0 + e1;
    #pragma unroll
    for (int off = 16; off > 0; off >>= 1)
        sden += __shfl_xor_sync(0xffffffffu, sden, off);
    float inv = 1.0f / sden;
    p[lane] = e0 * inv;
    p[lane + 32] = e1 * inv;
}

// ---------------- value head: out[m] = dot(V[m,:512], w) + b[0] ----------------
__global__ void matvec_val(const float* __restrict__ V, const float* __restrict__ w,
                           const float* __restrict__ bias, float* __restrict__ out) {
    const int row  = blockIdx.x * 8 + (threadIdx.x >> 5);
    const int lane = threadIdx.x & 31;
    const float* vr = V + (size_t)row * ACTH;
    float s = 0.0f;
    #pragma unroll
    for (int q = 0; q < 4; q++) {
        int k = q * 128 + lane * 4;
        float4 a = *(const float4*)&vr[k];
        float4 b = *(const float4*)&w[k];
        s = fmaf(a.x, b.x, s); s = fmaf(a.y, b.y, s);
        s = fmaf(a.z, b.z, s); s = fmaf(a.w, b.w, s);
    }
    #pragma unroll
    for (int off = 16; off > 0; off >>= 1)
        s += __shfl_xor_sync(0xffffffffu, s, off);
    if (lane == 0) out[row] = s + bias[0];
}

// ---------------- launch ----------------
extern "C" void kernel_launch(void* const* d_in, const int* in_sizes, int n_in,
                              void* d_out, int out_size) {
    const float* x        = (const float*)d_in[0];
    const float* pre_W0   = (const float*)d_in[1];
    const float* pre_b0   = (const float*)d_in[2];
    const float* pre_W1   = (const float*)d_in[3];
    const float* pre_b1   = (const float*)d_in[4];
    const float* w_ih     = (const float*)d_in[5];
    const float* w_hh     = (const float*)d_in[6];
    const float* b_ih     = (const float*)d_in[7];
    const float* b_hh     = (const float*)d_in[8];
    const float* act_W0   = (const float*)d_in[9];
    const float* act_b0   = (const float*)d_in[10];
    const float* act_W1   = (const float*)d_in[11];
    const float* act_b1   = (const float*)d_in[12];
    const float* val_W0   = (const float*)d_in[13];
    const float* val_b0   = (const float*)d_in[14];
    const float* val_W1   = (const float*)d_in[15];
    const float* val_b1   = (const float*)d_in[16];

    float* out_probs = (float*)d_out;
    float* out_value = (float*)d_out + (size_t)MTOT * NPOL;

    float *pH, *pU, *pXG, *pHS, *pA, *pV, *pHA, *pHB;
    cudaGetSymbolAddress((void**)&pH,  g_h);
    cudaGetSymbolAddress((void**)&pU,  g_u);
    cudaGetSymbolAddress((void**)&pXG, g_xg);
    cudaGetSymbolAddress((void**)&pHS, g_hs);
    cudaGetSymbolAddress((void**)&pA,  g_a);
    cudaGetSymbolAddress((void**)&pV,  g_v);
    cudaGetSymbolAddress((void**)&pHA, g_hstA);
    cudaGetSymbolAddress((void**)&pHB, g_hstB);

    cudaFuncSetAttribute(lstm_persist, cudaFuncAttributeMaxDynamicSharedMemorySize, RSMEM_BYTES);

    reset_bar<<<1, 1>>>();

    // pre_dnn
    sgemm128<true ><<<dim3(PRE_ / BN2, MTOT / BM2), 256>>>(x,  pre_W0, pre_b0, nullptr, pH, MTOT, PRE_, IN_);
    sgemm128<false><<<dim3(LH_  / BN2, MTOT / BM2), 256>>>(pH, pre_W1, pre_b1, nullptr, pU, MTOT, LH_, PRE_);

    // input contribution to gates (+ both biases)
    sgemm128<false><<<dim3(G4 / BN2, MTOT / BM2), 256>>>(pU, w_ih, b_ih, b_hh, pXG, MTOT, G4, LH_);

    // persistent recurrence (one launch for all 512 steps)
    lstm_persist<<<NBLK, RTPB, RSMEM_BYTES>>>(w_hh, pXG, pHA, pHB, pHS);

    // policy head
    sgemm128<true ><<<dim3(ACTH / BN2, MTOT / BM2), 256>>>(pHS, act_W0, act_b0, nullptr, pA, MTOT, ACTH, NHID);
    sgemm128<false><<<dim3(NPOL / BN2, MTOT / BM2), 256>>>(pA, act_W1, act_b1, nullptr, out_probs, MTOT, NPOL, ACTH);
    softmax64<<<MTOT / 4, 128>>>(out_probs);

    // value head
    sgemm128<true ><<<dim3(ACTH / BN2, MTOT / BM2), 256>>>(pHS, val_W0, val_b0, nullptr, pV, MTOT, ACTH, NHID);
    matvec_val<<<MTOT / 8, 256>>>(pV, val_W1, val_b1, out_value);
}

// round 10
// speedup vs baseline: 4.1032x; 1.1974x over previous
#include <cuda_runtime.h>
#include <math.h>

#define B_    32
#define T_    512
#define IN_   256
#define PRE_  512
#define LH_   512
#define NHID  1024
#define ACTH  512
#define NPOL  64
#define MTOT  (B_ * T_)      // 16384
#define G4    (4 * NHID)     // 4096

#define NBLK  128            // persistent blocks (<=148 SMs, co-resident)

// ---------------- scratch (device globals; no allocation allowed) ----------------
__device__ float g_h [(size_t)MTOT * PRE_];
__device__ float g_u [(size_t)MTOT * LH_];
__device__ float g_xg[(size_t)MTOT * G4];
__device__ float g_hs[(size_t)MTOT * NHID];
__device__ float g_a [(size_t)MTOT * ACTH];
__device__ float g_v [(size_t)MTOT * ACTH];
__device__ float g_hstA[B_ * NHID];
__device__ float g_hstB[B_ * NHID];
__device__ unsigned g_flags[NBLK];

__global__ void reset_flags() { if (threadIdx.x < NBLK) g_flags[threadIdx.x] = 0u; }

// ---------------- packed f32x2 helpers ----------------
__device__ __forceinline__ unsigned long long pk2(float lo, float hi) {
    unsigned long long r;
    asm("mov.b64 %0, {%1, %2};" : "=l"(r) : "f"(lo), "f"(hi));
    return r;
}
__device__ __forceinline__ void fma2(unsigned long long& d, unsigned long long a, unsigned long long b) {
    asm("fma.rn.f32x2 %0, %1, %2, %0;" : "+l"(d) : "l"(a), "l"(b));
}
__device__ __forceinline__ float2 upk(unsigned long long v) {
    float lo, hi;
    asm("mov.b64 {%0, %1}, %2;" : "=f"(lo), "=f"(hi) : "l"(v));
    return make_float2(lo, hi);
}

// ---------------- feedforward SGEMM: 128x64 tile, 8x4 micro, f32x2 ----------------
#define BK  16
#define BM2 128
#define BN2 64

template<bool RELU>
__global__ void __launch_bounds__(256)
sgemm128(const float* __restrict__ A, const float* __restrict__ W,
         const float* __restrict__ bias1, const float* __restrict__ bias2,
         float* __restrict__ C, int M, int N, int K)
{
    __shared__ float As[BK][BM2 + 4];
    __shared__ float Ws[BK][BN2 + 4];

    const int tid = threadIdx.x;
    const int tx = tid & 15;
    const int ty = tid >> 4;
    const int m0 = blockIdx.y * BM2;
    const int n0 = blockIdx.x * BN2;

    const int arow = tid >> 1, akq = (tid & 1) * 8;
    const int wrow = tid >> 2, wkq = (tid & 3) * 4;

    unsigned long long acc[4][4] = {};

    for (int k0 = 0; k0 < K; k0 += BK) {
        float4 a0 = *(const float4*)&A[(size_t)(m0 + arow) * K + k0 + akq];
        float4 a1 = *(const float4*)&A[(size_t)(m0 + arow) * K + k0 + akq + 4];
        float4 wv = *(const float4*)&W[(size_t)(n0 + wrow) * K + k0 + wkq];
        As[akq + 0][arow] = a0.x; As[akq + 1][arow] = a0.y;
        As[akq + 2][arow] = a0.z; As[akq + 3][arow] = a0.w;
        As[akq + 4][arow] = a1.x; As[akq + 5][arow] = a1.y;
        As[akq + 6][arow] = a1.z; As[akq + 7][arow] = a1.w;
        Ws[wkq + 0][wrow] = wv.x; Ws[wkq + 1][wrow] = wv.y;
        Ws[wkq + 2][wrow] = wv.z; Ws[wkq + 3][wrow] = wv.w;
        __syncthreads();

        #pragma unroll
        for (int kk = 0; kk < BK; kk++) {
            const ulonglong2* ap2 = (const ulonglong2*)&As[kk][ty * 8];
            ulonglong2 aA = ap2[0];
            ulonglong2 aB = ap2[1];
            unsigned long long ap[4] = { aA.x, aA.y, aB.x, aB.y };
            float4 w4 = *(const float4*)&Ws[kk][tx * 4];
            float wn[4] = {w4.x, w4.y, w4.z, w4.w};
            #pragma unroll
            for (int j = 0; j < 4; j++) {
                unsigned long long wd = pk2(wn[j], wn[j]);
                #pragma unroll
                for (int p = 0; p < 4; p++) fma2(acc[p][j], ap[p], wd);
            }
        }
        __syncthreads();
    }

    float4 bv = *(const float4*)&bias1[n0 + tx * 4];
    if (bias2) {
        float4 b2 = *(const float4*)&bias2[n0 + tx * 4];
        bv.x += b2.x; bv.y += b2.y; bv.z += b2.z; bv.w += b2.w;
    }
    float bn[4] = {bv.x, bv.y, bv.z, bv.w};

    #pragma unroll
    for (int p = 0; p < 4; p++) {
        float2 u0 = upk(acc[p][0]), u1 = upk(acc[p][1]);
        float2 u2 = upk(acc[p][2]), u3 = upk(acc[p][3]);
        float4 lo = {u0.x + bn[0], u1.x + bn[1], u2.x + bn[2], u3.x + bn[3]};
        float4 hi = {u0.y + bn[0], u1.y + bn[1], u2.y + bn[2], u3.y + bn[3]};
        if (RELU) {
            lo.x = fmaxf(lo.x, 0.f); lo.y = fmaxf(lo.y, 0.f);
            lo.z = fmaxf(lo.z, 0.f); lo.w = fmaxf(lo.w, 0.f);
            hi.x = fmaxf(hi.x, 0.f); hi.y = fmaxf(hi.y, 0.f);
            hi.z = fmaxf(hi.z, 0.f); hi.w = fmaxf(hi.w, 0.f);
        }
        *(float4*)&C[(size_t)(m0 + ty * 8 + 2 * p)     * N + n0 + tx * 4] = lo;
        *(float4*)&C[(size_t)(m0 + ty * 8 + 2 * p + 1) * N + n0 + tx * 4] = hi;
    }
}

// ---------------- grid-wide barrier: per-block flags, distributed polling ----------------
__device__ __forceinline__ void grid_bar2(int tid, unsigned epoch) {
    __threadfence();                 // order this thread's h stores before flag visibility
    __syncthreads();
    if (tid == 0) atomicExch(&g_flags[blockIdx.x], epoch);
    if (tid < NBLK) {
        while (__ldcg(&g_flags[tid]) < epoch) __nanosleep(32);
    }
    __syncthreads();
}

// ---------------- persistent LSTM recurrence, weights in registers ----------------
// 128 blocks x 256 threads (8 warps). Block owns units bid*8..+7 = 32 gate-rows.
// lane = gate-row r (u_off = r>>2, gate = r&3); warp w owns K-slice [w*128, w*128+128).
// Each thread holds its 128 weight floats in 64 b64 registers. h slices staged into
// per-warp private SMEM and consumed as 16B broadcasts. 8-way K reduction via padded
// SMEM; cell update by thread (u = warpid, b = lane); c-state in registers.
#define HST_F  (8 * 32 * 128)          // 32768 floats (16KB per warp)
#define RED_F  (8 * 32 * 33 + 32)      // 8480 floats, stride-33 padded
#define RSMEM_BYTES ((HST_F + RED_F) * 4)

__global__ void __launch_bounds__(256, 1)
lstm_persist(const float* __restrict__ Whh, const float* __restrict__ xg,
             float* __restrict__ hA, float* __restrict__ hB, float* __restrict__ hs)
{
    extern __shared__ float sm[];
    float* hst = sm;                    // [warp][32 b][128 k]
    float* red = sm + HST_F;            // [(w*32 + r)*33 + b]

    const int tid  = threadIdx.x;
    const int lane = tid & 31;
    const int w    = tid >> 5;
    const int bid  = blockIdx.x;

    // ---- weight registers: lane = gate-row, warp = K-slice ----
    const int uo   = lane >> 2;         // unit offset 0..7
    const int gate = lane & 3;          // i,f,g,o
    const float* wrow = Whh + ((size_t)(gate * NHID + bid * 8 + uo)) * NHID + w * 128;
    ulonglong2 wk[32];
    #pragma unroll
    for (int q = 0; q < 32; q++)
        wk[q] = *(const ulonglong2*)(wrow + q * 4);

    // ---- cell role: thread = (unit u = w, batch b = lane) ----
    const int u = w;
    const int b = lane;
    const int jg = bid * 8 + u;         // global unit index
    float c = 0.0f;
    hA[b * NHID + jg] = 0.0f;

    grid_bar2(tid, 1u);

    float* myh = hst + w * 4096;        // this warp's staging [32 b][128 k]

    for (int t = 0; t < T_; t++) {
        const float* hin = (t & 1) ? hB : hA;
        float*       hot = (t & 1) ? hA : hB;

        // prefetch gate biases (consumed after reduction)
        const float* xr = xg + ((size_t)b * T_ + t) * G4 + jg;
        float xi = __ldg(xr);
        float xf = __ldg(xr + NHID);
        float xG = __ldg(xr + 2 * NHID);
        float xo = __ldg(xr + 3 * NHID);

        // ---- stage my K-slice for all 32 batches (warp-private; coalesced LDG) ----
        {
            const float* src = hin + w * 128 + lane * 4;
            #pragma unroll
            for (int g8 = 0; g8 < 4; g8++) {
                float4 v[8];
                #pragma unroll
                for (int i = 0; i < 8; i++)
                    v[i] = __ldcg((const float4*)(src + (size_t)(g8 * 8 + i) * NHID));
                #pragma unroll
                for (int i = 0; i < 8; i++)
                    *(float4*)(myh + (g8 * 8 + i) * 128 + lane * 4) = v[i];
            }
        }
        __syncwarp();

        // ---- compute: dot(w_row[lane], h[bb][slice]) for each batch ----
        #pragma unroll 1
        for (int bb = 0; bb < 32; bb++) {
            const float* hb = myh + bb * 128;
            unsigned long long a0 = 0, a1 = 0;
            #pragma unroll
            for (int q = 0; q < 32; q++) {
                ulonglong2 hv = *(const ulonglong2*)(hb + q * 4);   // broadcast, 1 wf
                fma2(a0, wk[q].x, hv.x);
                fma2(a1, wk[q].y, hv.y);
            }
            float2 p0 = upk(a0), p1 = upk(a1);
            red[(w * 32 + lane) * 33 + bb] = (p0.x + p0.y) + (p1.x + p1.y);
        }
        __syncthreads();

        // ---- reduce 8 K-partials + cell update: thread (u, b) ----
        float s0 = 0.f, s1 = 0.f, s2 = 0.f, s3 = 0.f;
        #pragma unroll
        for (int ww = 0; ww < 8; ww++) {
            const float* rb = red + (ww * 32 + u * 4) * 33 + b;
            s0 += rb[0];
            s1 += rb[33];
            s2 += rb[66];
            s3 += rb[99];
        }
        float gi = s0 + xi, gf = s1 + xf, gg = s2 + xG, go = s3 + xo;

        float si = 1.0f / (1.0f + expf(-gi));
        float sf = 1.0f / (1.0f + expf(-gf));
        float so = 1.0f / (1.0f + expf(-go));

        c = sf * c + si * tanhf(gg);
        float h = so * tanhf(c);

        __stcg(&hot[b * NHID + jg], h);
        hs[((size_t)b * T_ + t) * NHID + jg] = h;

        grid_bar2(tid, (unsigned)(t + 2));
    }
}

// ---------------- softmax over last dim (64) in place ----------------
__global__ void softmax64(float* __restrict__ logits) {
    const int row  = blockIdx.x * 4 + (threadIdx.x >> 5);
    const int lane = threadIdx.x & 31;
    float* p = logits + (size_t)row * NPOL;
    float v0 = p[lane], v1 = p[lane + 32];
    float m = fmaxf(v0, v1);
    #pragma unroll
    for (int off = 16; off > 0; off >>= 1)
        m = fmaxf(m, __shfl_xor_sync(0xffffffffu, m, off));
    float e0 = expf(v0 - m), e1 = expf(v1 - m);
    float sden = e0 + e1;
    #pragma unroll
    for (int off = 16; off > 0; off >>= 1)
        sden += __shfl_xor_sync(0xffffffffu, sden, off);
    float inv = 1.0f / sden;
    p[lane] = e0 * inv;
    p[lane + 32] = e1 * inv;
}

// ---------------- value head: out[m] = dot(V[m,:512], w) + b[0] ----------------
__global__ void matvec_val(const float* __restrict__ V, const float* __restrict__ w,
                           const float* __restrict__ bias, float* __restrict__ out) {
    const int row  = blockIdx.x * 8 + (threadIdx.x >> 5);
    const int lane = threadIdx.x & 31;
    const float* vr = V + (size_t)row * ACTH;
    float s = 0.0f;
    #pragma unroll
    for (int q = 0; q < 4; q++) {
        int k = q * 128 + lane * 4;
        float4 a = *(const float4*)&vr[k];
        float4 b = *(const float4*)&w[k];
        s = fmaf(a.x, b.x, s); s = fmaf(a.y, b.y, s);
        s = fmaf(a.z, b.z, s); s = fmaf(a.w, b.w, s);
    }
    #pragma unroll
    for (int off = 16; off > 0; off >>= 1)
        s += __shfl_xor_sync(0xffffffffu, s, off);
    if (lane == 0) out[row] = s + bias[0];
}

// ---------------- launch ----------------
extern "C" void kernel_launch(void* const* d_in, const int* in_sizes, int n_in,
                              void* d_out, int out_size) {
    const float* x        = (const float*)d_in[0];
    const float* pre_W0   = (const float*)d_in[1];
    const float* pre_b0   = (const float*)d_in[2];
    const float* pre_W1   = (const float*)d_in[3];
    const float* pre_b1   = (const float*)d_in[4];
    const float* w_ih     = (const float*)d_in[5];
    const float* w_hh     = (const float*)d_in[6];
    const float* b_ih     = (const float*)d_in[7];
    const float* b_hh     = (const float*)d_in[8];
    const float* act_W0   = (const float*)d_in[9];
    const float* act_b0   = (const float*)d_in[10];
    const float* act_W1   = (const float*)d_in[11];
    const float* act_b1   = (const float*)d_in[12];
    const float* val_W0   = (const float*)d_in[13];
    const float* val_b0   = (const float*)d_in[14];
    const float* val_W1   = (const float*)d_in[15];
    const float* val_b1   = (const float*)d_in[16];

    float* out_probs = (float*)d_out;
    float* out_value = (float*)d_out + (size_t)MTOT * NPOL;

    float *pH, *pU, *pXG, *pHS, *pA, *pV, *pHA, *pHB;
    cudaGetSymbolAddress((void**)&pH,  g_h);
    cudaGetSymbolAddress((void**)&pU,  g_u);
    cudaGetSymbolAddress((void**)&pXG, g_xg);
    cudaGetSymbolAddress((void**)&pHS, g_hs);
    cudaGetSymbolAddress((void**)&pA,  g_a);
    cudaGetSymbolAddress((void**)&pV,  g_v);
    cudaGetSymbolAddress((void**)&pHA, g_hstA);
    cudaGetSymbolAddress((void**)&pHB, g_hstB);

    cudaFuncSetAttribute(lstm_persist, cudaFuncAttributeMaxDynamicSharedMemorySize, RSMEM_BYTES);

    reset_flags<<<1, 128>>>();

    // pre_dnn
    sgemm128<true ><<<dim3(PRE_ / BN2, MTOT / BM2), 256>>>(x,  pre_W0, pre_b0, nullptr, pH, MTOT, PRE_, IN_);
    sgemm128<false><<<dim3(LH_  / BN2, MTOT / BM2), 256>>>(pH, pre_W1, pre_b1, nullptr, pU, MTOT, LH_, PRE_);

    // input contribution to gates (+ both biases)
    sgemm128<false><<<dim3(G4 / BN2, MTOT / BM2), 256>>>(pU, w_ih, b_ih, b_hh, pXG, MTOT, G4, LH_);

    // persistent recurrence (one launch for all 512 steps)
    lstm_persist<<<NBLK, 256, RSMEM_BYTES>>>(w_hh, pXG, pHA, pHB, pHS);

    // policy head
    sgemm128<true ><<<dim3(ACTH / BN2, MTOT / BM2), 256>>>(pHS, act_W0, act_b0, nullptr, pA, MTOT, ACTH, NHID);
    sgemm128<false><<<dim3(NPOL / BN2, MTOT / BM2), 256>>>(pA, act_W1, act_b1, nullptr, out_probs, MTOT, NPOL, ACTH);
    softmax64<<<MTOT / 4, 128>>>(out_probs);

    // value head
    sgemm128<true ><<<dim3(ACTH / BN2, MTOT / BM2), 256>>>(pHS, val_W0, val_b0, nullptr, pV, MTOT, ACTH, NHID);
    matvec_val<<<MTOT / 8, 256>>>(pV, val_W1, val_b1, out_value);
}

// round 11
// speedup vs baseline: 4.2082x; 1.0256x over previous
#include <cuda_runtime.h>
#include <math.h>

#define B_    32
#define T_    512
#define IN_   256
#define PRE_  512
#define LH_   512
#define NHID  1024
#define ACTH  512
#define NPOL  64
#define MTOT  (B_ * T_)      // 16384
#define G4    (4 * NHID)     // 4096

#define NBLK  128            // persistent blocks (<=148 SMs, co-resident)

// ---------------- scratch (device globals; no allocation allowed) ----------------
__device__ float g_h [(size_t)MTOT * PRE_];
__device__ float g_u [(size_t)MTOT * LH_];
__device__ float g_xg[(size_t)MTOT * G4];
__device__ float g_hs[(size_t)MTOT * NHID];
__device__ float g_a [(size_t)MTOT * ACTH];
__device__ float g_v [(size_t)MTOT * ACTH];
__device__ float g_hstA[B_ * NHID];
__device__ float g_hstB[B_ * NHID];
__device__ unsigned g_flags[NBLK];

__global__ void reset_flags() { if (threadIdx.x < NBLK) g_flags[threadIdx.x] = 0u; }

// ---------------- packed f32x2 helpers ----------------
__device__ __forceinline__ unsigned long long pk2(float lo, float hi) {
    unsigned long long r;
    asm("mov.b64 %0, {%1, %2};" : "=l"(r) : "f"(lo), "f"(hi));
    return r;
}
__device__ __forceinline__ void fma2(unsigned long long& d, unsigned long long a, unsigned long long b) {
    asm("fma.rn.f32x2 %0, %1, %2, %0;" : "+l"(d) : "l"(a), "l"(b));
}
__device__ __forceinline__ float2 upk(unsigned long long v) {
    float lo, hi;
    asm("mov.b64 {%0, %1}, %2;" : "=f"(lo), "=f"(hi) : "l"(v));
    return make_float2(lo, hi);
}

// ---------------- feedforward SGEMM: 128x64 tile, double-buffered smem ----------------
#define BK  16
#define BM2 128
#define BN2 64

template<bool RELU>
__global__ void __launch_bounds__(256)
sgemm128(const float* __restrict__ A, const float* __restrict__ W,
         const float* __restrict__ bias1, const float* __restrict__ bias2,
         float* __restrict__ C, int M, int N, int K)
{
    __shared__ float As[2][BK][BM2 + 4];
    __shared__ float Ws[2][BK][BN2 + 4];

    const int tid = threadIdx.x;
    const int tx = tid & 15;
    const int ty = tid >> 4;
    const int m0 = blockIdx.y * BM2;
    const int n0 = blockIdx.x * BN2;

    const int arow = tid >> 1, akq = (tid & 1) * 8;
    const int wrow = tid >> 2, wkq = (tid & 3) * 4;

    const float* Abase = &A[(size_t)(m0 + arow) * K + akq];
    const float* Wbase = &W[(size_t)(n0 + wrow) * K + wkq];

    unsigned long long acc[4][4] = {};

    // preload tile 0
    {
        float4 a0 = *(const float4*)(Abase);
        float4 a1 = *(const float4*)(Abase + 4);
        float4 wv = *(const float4*)(Wbase);
        As[0][akq + 0][arow] = a0.x; As[0][akq + 1][arow] = a0.y;
        As[0][akq + 2][arow] = a0.z; As[0][akq + 3][arow] = a0.w;
        As[0][akq + 4][arow] = a1.x; As[0][akq + 5][arow] = a1.y;
        As[0][akq + 6][arow] = a1.z; As[0][akq + 7][arow] = a1.w;
        Ws[0][wkq + 0][wrow] = wv.x; Ws[0][wkq + 1][wrow] = wv.y;
        Ws[0][wkq + 2][wrow] = wv.z; Ws[0][wkq + 3][wrow] = wv.w;
    }
    __syncthreads();

    int buf = 0;
    for (int k0 = 0; k0 < K; k0 += BK) {
        // prefetch next tile into registers
        float4 na0, na1, nwv;
        const bool more = (k0 + BK) < K;
        if (more) {
            na0 = *(const float4*)(Abase + k0 + BK);
            na1 = *(const float4*)(Abase + k0 + BK + 4);
            nwv = *(const float4*)(Wbase + k0 + BK);
        }

        #pragma unroll
        for (int kk = 0; kk < BK; kk++) {
            const ulonglong2* ap2 = (const ulonglong2*)&As[buf][kk][ty * 8];
            ulonglong2 aA = ap2[0];
            ulonglong2 aB = ap2[1];
            unsigned long long ap[4] = { aA.x, aA.y, aB.x, aB.y };
            float4 w4 = *(const float4*)&Ws[buf][kk][tx * 4];
            float wn[4] = {w4.x, w4.y, w4.z, w4.w};
            #pragma unroll
            for (int j = 0; j < 4; j++) {
                unsigned long long wd = pk2(wn[j], wn[j]);
                #pragma unroll
                for (int p = 0; p < 4; p++) fma2(acc[p][j], ap[p], wd);
            }
        }

        if (more) {
            const int nb = buf ^ 1;
            As[nb][akq + 0][arow] = na0.x; As[nb][akq + 1][arow] = na0.y;
            As[nb][akq + 2][arow] = na0.z; As[nb][akq + 3][arow] = na0.w;
            As[nb][akq + 4][arow] = na1.x; As[nb][akq + 5][arow] = na1.y;
            As[nb][akq + 6][arow] = na1.z; As[nb][akq + 7][arow] = na1.w;
            Ws[nb][wkq + 0][wrow] = nwv.x; Ws[nb][wkq + 1][wrow] = nwv.y;
            Ws[nb][wkq + 2][wrow] = nwv.z; Ws[nb][wkq + 3][wrow] = nwv.w;
            __syncthreads();
        }
        buf ^= 1;
    }

    float4 bv = *(const float4*)&bias1[n0 + tx * 4];
    if (bias2) {
        float4 b2 = *(const float4*)&bias2[n0 + tx * 4];
        bv.x += b2.x; bv.y += b2.y; bv.z += b2.z; bv.w += b2.w;
    }
    float bn[4] = {bv.x, bv.y, bv.z, bv.w};

    #pragma unroll
    for (int p = 0; p < 4; p++) {
        float2 u0 = upk(acc[p][0]), u1 = upk(acc[p][1]);
        float2 u2 = upk(acc[p][2]), u3 = upk(acc[p][3]);
        float4 lo = {u0.x + bn[0], u1.x + bn[1], u2.x + bn[2], u3.x + bn[3]};
        float4 hi = {u0.y + bn[0], u1.y + bn[1], u2.y + bn[2], u3.y + bn[3]};
        if (RELU) {
            lo.x = fmaxf(lo.x, 0.f); lo.y = fmaxf(lo.y, 0.f);
            lo.z = fmaxf(lo.z, 0.f); lo.w = fmaxf(lo.w, 0.f);
            hi.x = fmaxf(hi.x, 0.f); hi.y = fmaxf(hi.y, 0.f);
            hi.z = fmaxf(hi.z, 0.f); hi.w = fmaxf(hi.w, 0.f);
        }
        *(float4*)&C[(size_t)(m0 + ty * 8 + 2 * p)     * N + n0 + tx * 4] = lo;
        *(float4*)&C[(size_t)(m0 + ty * 8 + 2 * p + 1) * N + n0 + tx * 4] = hi;
    }
}

// ---------------- grid-wide barrier: per-block flags, distributed polling ----------------
__device__ __forceinline__ void grid_bar2(int tid, unsigned epoch) {
    __threadfence();
    __syncthreads();
    if (tid == 0) atomicExch(&g_flags[blockIdx.x], epoch);
    if (tid < NBLK) {
        while (__ldcg(&g_flags[tid]) < epoch) __nanosleep(32);
    }
    __syncthreads();
}

// ---------------- persistent LSTM recurrence, weights in registers ----------------
// 128 blocks x 256 threads (8 warps). Block owns units bid*8..+7 = 32 gate-rows.
// lane = gate-row r (u_off = r>>2, gate = r&3); warp w owns K-slice [w*128, w*128+128).
// Thread holds 128 weight floats in 64 b64 registers. h staged per warp in quarters
// (8 batches) pipelined against compute. 8-way K reduce via padded SMEM; cell update
// by thread (u = warpid, b = lane); c-state in registers.
#define HST_F  (8 * 32 * 128)          // 32768 floats
#define RED_F  (8 * 32 * 33 + 32)      // padded
#define RSMEM_BYTES ((HST_F + RED_F) * 4)

__global__ void __launch_bounds__(256, 1)
lstm_persist(const float* __restrict__ Whh, const float* __restrict__ xg,
             float* __restrict__ hA, float* __restrict__ hB, float* __restrict__ hs)
{
    extern __shared__ float sm[];
    float* hst = sm;                    // [warp][32 b][128 k]
    float* red = sm + HST_F;            // [(w*32 + r)*33 + b]

    const int tid  = threadIdx.x;
    const int lane = tid & 31;
    const int w    = tid >> 5;
    const int bid  = blockIdx.x;

    // ---- weight registers: lane = gate-row, warp = K-slice ----
    const int uo   = lane >> 2;
    const int gate = lane & 3;
    const float* wrow = Whh + ((size_t)(gate * NHID + bid * 8 + uo)) * NHID + w * 128;
    ulonglong2 wk[32];
    #pragma unroll
    for (int q = 0; q < 32; q++)
        wk[q] = *(const ulonglong2*)(wrow + q * 4);

    // ---- cell role: thread = (unit u = w, batch b = lane) ----
    const int u = w;
    const int b = lane;
    const int jg = bid * 8 + u;
    float c = 0.0f;
    hA[b * NHID + jg] = 0.0f;

    grid_bar2(tid, 1u);

    float* myh = hst + w * 4096;

    for (int t = 0; t < T_; t++) {
        const float* hin = (t & 1) ? hB : hA;
        float*       hot = (t & 1) ? hA : hB;

        // gate biases (independent; consumed after reduction)
        const float* xr = xg + ((size_t)b * T_ + t) * G4 + jg;
        float xi = __ldg(xr);
        float xf = __ldg(xr + NHID);
        float xG = __ldg(xr + 2 * NHID);
        float xo = __ldg(xr + 3 * NHID);

        const float* src = hin + w * 128 + lane * 4;

        // stage quarter 0 (batches 0..7)
        {
            float4 v[8];
            #pragma unroll
            for (int i = 0; i < 8; i++)
                v[i] = __ldcg((const float4*)(src + (size_t)i * NHID));
            #pragma unroll
            for (int i = 0; i < 8; i++)
                *(float4*)(myh + i * 128 + lane * 4) = v[i];
        }
        __syncwarp();

        // pipelined quarters: prefetch qt+1 while computing qt
        #pragma unroll 1
        for (int qt = 0; qt < 4; qt++) {
            float4 nv[8];
            if (qt < 3) {
                #pragma unroll
                for (int i = 0; i < 8; i++)
                    nv[i] = __ldcg((const float4*)(src + (size_t)((qt + 1) * 8 + i) * NHID));
            }

            #pragma unroll 1
            for (int bq = 0; bq < 8; bq++) {
                const int bb = qt * 8 + bq;
                const float* hb = myh + bb * 128;
                unsigned long long a0 = 0, a1 = 0;
                #pragma unroll
                for (int q = 0; q < 32; q++) {
                    ulonglong2 hv = *(const ulonglong2*)(hb + q * 4);  // 16B broadcast
                    fma2(a0, wk[q].x, hv.x);
                    fma2(a1, wk[q].y, hv.y);
                }
                float2 p0 = upk(a0), p1 = upk(a1);
                red[(w * 32 + lane) * 33 + bb] = (p0.x + p0.y) + (p1.x + p1.y);
            }

            if (qt < 3) {
                #pragma unroll
                for (int i = 0; i < 8; i++)
                    *(float4*)(myh + ((qt + 1) * 8 + i) * 128 + lane * 4) = nv[i];
                __syncwarp();
            }
        }
        __syncthreads();

        // ---- reduce 8 K-partials + cell update: thread (u, b) ----
        float s0 = 0.f, s1 = 0.f, s2 = 0.f, s3 = 0.f;
        #pragma unroll
        for (int ww = 0; ww < 8; ww++) {
            const float* rb = red + (ww * 32 + u * 4) * 33 + b;
            s0 += rb[0];
            s1 += rb[33];
            s2 += rb[66];
            s3 += rb[99];
        }
        float gi = s0 + xi, gf = s1 + xf, gg = s2 + xG, go = s3 + xo;

        float si = 1.0f / (1.0f + expf(-gi));
        float sf = 1.0f / (1.0f + expf(-gf));
        float so = 1.0f / (1.0f + expf(-go));

        c = sf * c + si * tanhf(gg);
        float h = so * tanhf(c);

        __stcg(&hot[b * NHID + jg], h);
        hs[((size_t)b * T_ + t) * NHID + jg] = h;

        grid_bar2(tid, (unsigned)(t + 2));
    }
}

// ---------------- softmax over last dim (64) in place ----------------
__global__ void softmax64(float* __restrict__ logits) {
    const int row  = blockIdx.x * 4 + (threadIdx.x >> 5);
    const int lane = threadIdx.x & 31;
    float* p = logits + (size_t)row * NPOL;
    float v0 = p[lane], v1 = p[lane + 32];
    float m = fmaxf(v0, v1);
    #pragma unroll
    for (int off = 16; off > 0; off >>= 1)
        m = fmaxf(m, __shfl_xor_sync(0xffffffffu, m, off));
    float e0 = expf(v0 - m), e1 = expf(v1 - m);
    float sden = e0 + e1;
    #pragma unroll
    for (int off = 16; off > 0; off >>= 1)
        sden += __shfl_xor_sync(0xffffffffu, sden, off);
    float inv = 1.0f / sden;
    p[lane] = e0 * inv;
    p[lane + 32] = e1 * inv;
}

// ---------------- value head: out[m] = dot(V[m,:512], w) + b[0] ----------------
__global__ void matvec_val(const float* __restrict__ V, const float* __restrict__ w,
                           const float* __restrict__ bias, float* __restrict__ out) {
    const int row  = blockIdx.x * 8 + (threadIdx.x >> 5);
    const int lane = threadIdx.x & 31;
    const float* vr = V + (size_t)row * ACTH;
    float s = 0.0f;
    #pragma unroll
    for (int q = 0; q < 4; q++) {
        int k = q * 128 + lane * 4;
        float4 a = *(const float4*)&vr[k];
        float4 b = *(const float4*)&w[k];
        s = fmaf(a.x, b.x, s); s = fmaf(a.y, b.y, s);
        s = fmaf(a.z, b.z, s); s = fmaf(a.w, b.w, s);
    }
    #pragma unroll
    for (int off = 16; off > 0; off >>= 1)
        s += __shfl_xor_sync(0xffffffffu, s, off);
    if (lane == 0) out[row] = s + bias[0];
}

// ---------------- launch ----------------
extern "C" void kernel_launch(void* const* d_in, const int* in_sizes, int n_in,
                              void* d_out, int out_size) {
    const float* x        = (const float*)d_in[0];
    const float* pre_W0   = (const float*)d_in[1];
    const float* pre_b0   = (const float*)d_in[2];
    const float* pre_W1   = (const float*)d_in[3];
    const float* pre_b1   = (const float*)d_in[4];
    const float* w_ih     = (const float*)d_in[5];
    const float* w_hh     = (const float*)d_in[6];
    const float* b_ih     = (const float*)d_in[7];
    const float* b_hh     = (const float*)d_in[8];
    const float* act_W0   = (const float*)d_in[9];
    const float* act_b0   = (const float*)d_in[10];
    const float* act_W1   = (const float*)d_in[11];
    const float* act_b1   = (const float*)d_in[12];
    const float* val_W0   = (const float*)d_in[13];
    const float* val_b0   = (const float*)d_in[14];
    const float* val_W1   = (const float*)d_in[15];
    const float* val_b1   = (const float*)d_in[16];

    float* out_probs = (float*)d_out;
    float* out_value = (float*)d_out + (size_t)MTOT * NPOL;

    float *pH, *pU, *pXG, *pHS, *pA, *pV, *pHA, *pHB;
    cudaGetSymbolAddress((void**)&pH,  g_h);
    cudaGetSymbolAddress((void**)&pU,  g_u);
    cudaGetSymbolAddress((void**)&pXG, g_xg);
    cudaGetSymbolAddress((void**)&pHS, g_hs);
    cudaGetSymbolAddress((void**)&pA,  g_a);
    cudaGetSymbolAddress((void**)&pV,  g_v);
    cudaGetSymbolAddress((void**)&pHA, g_hstA);
    cudaGetSymbolAddress((void**)&pHB, g_hstB);

    cudaFuncSetAttribute(lstm_persist, cudaFuncAttributeMaxDynamicSharedMemorySize, RSMEM_BYTES);

    reset_flags<<<1, 128>>>();

    // pre_dnn
    sgemm128<true ><<<dim3(PRE_ / BN2, MTOT / BM2), 256>>>(x,  pre_W0, pre_b0, nullptr, pH, MTOT, PRE_, IN_);
    sgemm128<false><<<dim3(LH_  / BN2, MTOT / BM2), 256>>>(pH, pre_W1, pre_b1, nullptr, pU, MTOT, LH_, PRE_);

    // input contribution to gates (+ both biases)
    sgemm128<false><<<dim3(G4 / BN2, MTOT / BM2), 256>>>(pU, w_ih, b_ih, b_hh, pXG, MTOT, G4, LH_);

    // persistent recurrence (one launch for all 512 steps)
    lstm_persist<<<NBLK, 256, RSMEM_BYTES>>>(w_hh, pXG, pHA, pHB, pHS);

    // policy head
    sgemm128<true ><<<dim3(ACTH / BN2, MTOT / BM2), 256>>>(pHS, act_W0, act_b0, nullptr, pA, MTOT, ACTH, NHID);
    sgemm128<false><<<dim3(NPOL / BN2, MTOT / BM2), 256>>>(pA, act_W1, act_b1, nullptr, out_probs, MTOT, NPOL, ACTH);
    softmax64<<<MTOT / 4, 128>>>(out_probs);

    // value head
    sgemm128<true ><<<dim3(ACTH / BN2, MTOT / BM2), 256>>>(pHS, val_W0, val_b0, nullptr, pV, MTOT, ACTH, NHID);
    matvec_val<<<MTOT / 8, 256>>>(pV, val_W1, val_b1, out_value);
}